// round 1
// baseline (speedup 1.0000x reference)
#include <cuda_runtime.h>
#include <math.h>
#include <stdint.h>

// Problem constants (fixed by the reference)
constexpr int B   = 256;
constexpr int S   = 512;
constexpr int T   = B * S;       // 131072 tokens
constexpr int MEM = 32;
constexpr int DK  = 128;
constexpr int DV  = 128;
constexpr int DS  = 256;

// ---------------- scratch (static device allocations; no cudaMalloc) ----------------
__device__ float g_w      [(size_t)T * MEM];   // softmax attention weights
__device__ float g_erase  [(size_t)T * DV];
__device__ float g_add    [(size_t)T * DV];
__device__ float g_reads  [(size_t)T * DV];
__device__ float g_summary[(size_t)T * DS];
__device__ float g_h      [(size_t)T * DS];
__device__ float g_d1     [(size_t)T * DK];

// ---------------- attention logits + softmax (warp per token) ----------------
// w[t,m] = softmax_m( sum_k qe[t,k] * key_memory[m,k] )
__global__ __launch_bounds__(256) void attn_kernel(
    const int* __restrict__ q_data,
    const float* __restrict__ q_table,
    const float* __restrict__ key_memory,
    float* __restrict__ w_out)
{
    __shared__ float ksm[32 * 129];   // padded: bank (m + k) % 32, conflict-free
    int tid = threadIdx.x;
    for (int i = tid; i < 32 * 128; i += 256) {
        int m = i >> 7, k = i & 127;
        ksm[m * 129 + k] = key_memory[i];
    }
    __syncthreads();

    int warp = tid >> 5, lane = tid & 31;
    int t = blockIdx.x * 8 + warp;
    int row = q_data[t];

    float q0 = q_table[(size_t)row * 128 + lane];
    float q1 = q_table[(size_t)row * 128 + lane + 32];
    float q2 = q_table[(size_t)row * 128 + lane + 64];
    float q3 = q_table[(size_t)row * 128 + lane + 96];

    float lg = 0.f;
    #pragma unroll
    for (int k = 0; k < 128; ++k) {
        float qv;
        if (k < 32)       qv = __shfl_sync(0xffffffffu, q0, k & 31);
        else if (k < 64)  qv = __shfl_sync(0xffffffffu, q1, k & 31);
        else if (k < 96)  qv = __shfl_sync(0xffffffffu, q2, k & 31);
        else              qv = __shfl_sync(0xffffffffu, q3, k & 31);
        lg = fmaf(qv, ksm[lane * 129 + k], lg);
    }
    // softmax over 32 lanes
    float mx = lg;
    #pragma unroll
    for (int off = 16; off > 0; off >>= 1)
        mx = fmaxf(mx, __shfl_xor_sync(0xffffffffu, mx, off));
    float e = expf(lg - mx);
    float sum = e;
    #pragma unroll
    for (int off = 16; off > 0; off >>= 1)
        sum += __shfl_xor_sync(0xffffffffu, sum, off);
    w_out[(size_t)t * 32 + lane] = e / sum;
}

// ---------------- generic token-GEMM with optional gather and activation ----------------
// out[t, n] = act( sum_k A[t, k] * W[k, n] + bias[n] )
// A is defined in K-chunks of 128 columns; chunk 0 comes from (A0, idx0, w0, off0),
// chunk 1 from (A1, idx1, w1, off1). Row index = idx ? idx[t] : t.
// ACT: 0 = identity, 1 = sigmoid, 2 = tanh
template<int ACT>
__device__ __forceinline__ float act_apply(float x) {
    if (ACT == 1) return 1.f / (1.f + expf(-x));
    if (ACT == 2) return tanhf(x);
    return x;
}

template<int ACT>
__global__ __launch_bounds__(256, 2) void gemm_tok(
    const float* __restrict__ A0, const int* __restrict__ idx0, int w0, int off0,
    const float* __restrict__ A1, const int* __restrict__ idx1, int w1, int off1,
    int nkc,
    const float* __restrict__ W, int N,
    const float* __restrict__ bias,
    float* __restrict__ out)
{
    extern __shared__ float sm[];
    float4* Asm = (float4*)sm;                  // 64 rows x 32 float4  (32 KB)
    float4* Wsm = (float4*)(sm + 64 * 128);     // 128 rows x 32 float4 (64 KB)
    __shared__ int rows[2][64];

    int tid  = threadIdx.x;
    int tok0 = blockIdx.x * 64;
    int n0   = blockIdx.y * 128;

    if (tid < 64) {
        rows[0][tid] = idx0 ? idx0[tok0 + tid] : (tok0 + tid);
    } else if (tid < 128 && nkc > 1) {
        int r = tid - 64;
        rows[1][r] = idx1 ? idx1[tok0 + r] : (tok0 + r);
    }
    __syncthreads();

    float acc[8][4];
    #pragma unroll
    for (int i = 0; i < 8; ++i)
        #pragma unroll
        for (int u = 0; u < 4; ++u) acc[i][u] = 0.f;

    int cg = tid & 31;   // column group: 4 consecutive output cols
    int tg = tid >> 5;   // token group: 8 consecutive tokens

    for (int c = 0; c < nkc; ++c) {
        const float* base = (c == 0) ? A0 : A1;
        int wdt           = (c == 0) ? w0 : w1;
        int cof           = (c == 0) ? off0 : off1;
        const int* rw     = rows[(c == 0) ? 0 : 1];

        #pragma unroll
        for (int j = 0; j < 8; ++j) {          // A chunk: 64x128 fp32 = 512 float4
            int fid = tid + j * 256;
            int r = fid >> 5, c4 = fid & 31;
            Asm[r * 32 + c4] = *(const float4*)(base + (size_t)rw[r] * wdt + cof + c4 * 4);
        }
        #pragma unroll
        for (int j = 0; j < 16; ++j) {         // W chunk: 128x128 fp32 = 1024 float4
            int fid = tid + j * 256;
            int r = fid >> 5, c4 = fid & 31;
            Wsm[r * 32 + c4] = *(const float4*)(W + (size_t)(c * 128 + r) * N + n0 + c4 * 4);
        }
        __syncthreads();

        #pragma unroll
        for (int kk = 0; kk < 128; kk += 4) {
            float4 wv0 = Wsm[(kk + 0) * 32 + cg];
            float4 wv1 = Wsm[(kk + 1) * 32 + cg];
            float4 wv2 = Wsm[(kk + 2) * 32 + cg];
            float4 wv3 = Wsm[(kk + 3) * 32 + cg];
            #pragma unroll
            for (int i = 0; i < 8; ++i) {
                float4 a = Asm[(tg * 8 + i) * 32 + (kk >> 2)];  // broadcast within warp
                acc[i][0] = fmaf(a.x, wv0.x, acc[i][0]);
                acc[i][1] = fmaf(a.x, wv0.y, acc[i][1]);
                acc[i][2] = fmaf(a.x, wv0.z, acc[i][2]);
                acc[i][3] = fmaf(a.x, wv0.w, acc[i][3]);
                acc[i][0] = fmaf(a.y, wv1.x, acc[i][0]);
                acc[i][1] = fmaf(a.y, wv1.y, acc[i][1]);
                acc[i][2] = fmaf(a.y, wv1.z, acc[i][2]);
                acc[i][3] = fmaf(a.y, wv1.w, acc[i][3]);
                acc[i][0] = fmaf(a.z, wv2.x, acc[i][0]);
                acc[i][1] = fmaf(a.z, wv2.y, acc[i][1]);
                acc[i][2] = fmaf(a.z, wv2.z, acc[i][2]);
                acc[i][3] = fmaf(a.z, wv2.w, acc[i][3]);
                acc[i][0] = fmaf(a.w, wv3.x, acc[i][0]);
                acc[i][1] = fmaf(a.w, wv3.y, acc[i][1]);
                acc[i][2] = fmaf(a.w, wv3.z, acc[i][2]);
                acc[i][3] = fmaf(a.w, wv3.w, acc[i][3]);
            }
        }
        __syncthreads();
    }

    float4 bv = *(const float4*)(bias + n0 + cg * 4);
    #pragma unroll
    for (int i = 0; i < 8; ++i) {
        int t = tok0 + tg * 8 + i;
        float4 o;
        o.x = act_apply<ACT>(acc[i][0] + bv.x);
        o.y = act_apply<ACT>(acc[i][1] + bv.y);
        o.z = act_apply<ACT>(acc[i][2] + bv.z);
        o.w = act_apply<ACT>(acc[i][3] + bv.w);
        *(float4*)(out + (size_t)t * N + n0 + cg * 4) = o;
    }
}

// ---------------- DKVMN sequential scan: one block per batch element ----------------
// Thread d owns column d of Mv[32][128] in registers (32 floats).
// read[d] = sum_m w[m]*Mv[m][d];  Mv[m][d] += w[m]*(a[d] - Mv[m][d]*e[d])
__global__ __launch_bounds__(128) void scan_kernel(
    const float* __restrict__ init_value_memory)
{
    int b = blockIdx.x;
    int d = threadIdx.x;
    size_t tb = (size_t)b * S;

    float Mv[32];
    #pragma unroll
    for (int m = 0; m < 32; ++m)
        Mv[m] = init_value_memory[m * 128 + d];

    __shared__ float wsm[2][32];

    // preload step 0
    if (d < 32) wsm[0][d] = g_w[tb * 32 + d];
    float e = g_erase[tb * 128 + d];
    float a = g_add  [tb * 128 + d];
    __syncthreads();

    for (int s = 0; s < S; ++s) {
        int cur = s & 1, nxt = cur ^ 1;
        float e_n = 0.f, a_n = 0.f;
        if (s + 1 < S) {
            if (d < 32) wsm[nxt][d] = g_w[(tb + s + 1) * 32 + d];
            e_n = g_erase[(tb + s + 1) * 128 + d];
            a_n = g_add  [(tb + s + 1) * 128 + d];
        }
        float r = 0.f;
        #pragma unroll
        for (int m = 0; m < 32; ++m) {
            float wm = wsm[cur][m];
            r = fmaf(wm, Mv[m], r);                       // read BEFORE write
            Mv[m] = fmaf(wm, fmaf(-Mv[m], e, a), Mv[m]);  // Mv + w*(a - Mv*e)
        }
        g_reads[(tb + s) * 128 + d] = r;
        e = e_n; a = a_n;
        __syncthreads();
    }
}

// ---------------- final heads: warp per token ----------------
__global__ __launch_bounds__(128) void head_kernel(
    const float* __restrict__ W_ab2, const float* __restrict__ b_ab2,
    const float* __restrict__ W_df2, const float* __restrict__ b_df2,
    float* __restrict__ out)
{
    int warp = threadIdx.x >> 5, lane = threadIdx.x & 31;
    int t = blockIdx.x * 4 + warp;

    float pa = 0.f;
    #pragma unroll
    for (int j = 0; j < 8; ++j) {
        int k = lane + 32 * j;
        pa = fmaf(g_h[(size_t)t * 256 + k], W_ab2[k], pa);
    }
    float pd = 0.f;
    #pragma unroll
    for (int j = 0; j < 4; ++j) {
        int k = lane + 32 * j;
        pd = fmaf(g_d1[(size_t)t * 128 + k], W_df2[k], pd);
    }
    #pragma unroll
    for (int off = 16; off > 0; off >>= 1) {
        pa += __shfl_xor_sync(0xffffffffu, pa, off);
        pd += __shfl_xor_sync(0xffffffffu, pd, off);
    }
    if (lane == 0) {
        float ability    = pa + b_ab2[0];
        float difficulty = pd + b_df2[0];
        float z    = 3.0f * ability - difficulty;
        float pred = 1.f / (1.f + expf(-z));
        out[t]              = pred;
        out[(size_t)T + t]  = ability;
        out[(size_t)2*T + t] = difficulty;
        out[(size_t)3*T + t] = z;
    }
}

// ---------------- host launch ----------------
extern "C" void kernel_launch(void* const* d_in, const int* in_sizes, int n_in,
                              void* d_out, int out_size)
{
    const int*   q_data   = (const int*)  d_in[0];
    const int*   qa_data  = (const int*)  d_in[1];
    const float* q_table  = (const float*)d_in[2];
    const float* qa_table = (const float*)d_in[3];
    const float* key_mem  = (const float*)d_in[4];
    const float* init_vm  = (const float*)d_in[5];
    const float* W_erase  = (const float*)d_in[6];
    const float* b_erase  = (const float*)d_in[7];
    const float* W_add    = (const float*)d_in[8];
    const float* b_add    = (const float*)d_in[9];
    const float* W_sum    = (const float*)d_in[10];
    const float* b_sum    = (const float*)d_in[11];
    const float* W_ab1    = (const float*)d_in[12];
    const float* b_ab1    = (const float*)d_in[13];
    const float* W_ab2    = (const float*)d_in[14];
    const float* b_ab2    = (const float*)d_in[15];
    const float* W_df1    = (const float*)d_in[16];
    const float* b_df1    = (const float*)d_in[17];
    const float* W_df2    = (const float*)d_in[18];
    const float* b_df2    = (const float*)d_in[19];
    float* out = (float*)d_out;

    float *pw, *per, *pad, *prd, *psm, *ph, *pd1;
    cudaGetSymbolAddress((void**)&pw,  g_w);
    cudaGetSymbolAddress((void**)&per, g_erase);
    cudaGetSymbolAddress((void**)&pad, g_add);
    cudaGetSymbolAddress((void**)&prd, g_reads);
    cudaGetSymbolAddress((void**)&psm, g_summary);
    cudaGetSymbolAddress((void**)&ph,  g_h);
    cudaGetSymbolAddress((void**)&pd1, g_d1);

    constexpr int SMEM = (64 * 128 + 128 * 128) * 4;  // 96 KB
    cudaFuncSetAttribute(gemm_tok<1>, cudaFuncAttributeMaxDynamicSharedMemorySize, SMEM);
    cudaFuncSetAttribute(gemm_tok<2>, cudaFuncAttributeMaxDynamicSharedMemorySize, SMEM);

    // 1. attention softmax weights
    attn_kernel<<<T / 8, 256>>>(q_data, q_table, key_mem, pw);

    // 2. erase = sigmoid(qae @ W_erase + b), add = tanh(qae @ W_add + b)
    gemm_tok<1><<<dim3(T / 64, 1), 256, SMEM>>>(
        qa_table, qa_data, DV, 0,  nullptr, nullptr, 0, 0,  1, W_erase, DV, b_erase, per);
    gemm_tok<2><<<dim3(T / 64, 1), 256, SMEM>>>(
        qa_table, qa_data, DV, 0,  nullptr, nullptr, 0, 0,  1, W_add, DV, b_add, pad);

    // 3. difficulty hidden = tanh(qe @ W_df1 + b)  (independent of scan)
    gemm_tok<2><<<dim3(T / 64, 1), 256, SMEM>>>(
        q_table, q_data, DK, 0,  nullptr, nullptr, 0, 0,  1, W_df1, DK, b_df1, pd1);

    // 4. sequential DKVMN scan -> reads
    scan_kernel<<<B, 128>>>(init_vm);

    // 5. summary = tanh(concat(reads, qe) @ W_sum + b)   K=256 (chunk0: reads, chunk1: gathered qe)
    gemm_tok<2><<<dim3(T / 64, 2), 256, SMEM>>>(
        prd, nullptr, DV, 0,  q_table, q_data, DK, 0,  2, W_sum, DS, b_sum, psm);

    // 6. ability hidden = tanh(summary @ W_ab1 + b)      K=256 (both chunks from g_summary)
    gemm_tok<2><<<dim3(T / 64, 2), 256, SMEM>>>(
        psm, nullptr, DS, 0,  psm, nullptr, DS, 128,  2, W_ab1, DS, b_ab1, ph);

    // 7. heads + final outputs (pred, ability, difficulty, z)
    head_kernel<<<T / 4, 128>>>(W_ab2, b_ab2, W_df2, b_df2, out);
}

// round 3
// speedup vs baseline: 1.6169x; 1.6169x over previous
#include <cuda_runtime.h>
#include <cuda_bf16.h>
#include <math.h>
#include <stdint.h>

// Problem constants
constexpr int B   = 256;
constexpr int S   = 512;
constexpr int T   = B * S;       // 131072 tokens
constexpr int MEM = 32;
constexpr int DK  = 128;
constexpr int DV  = 128;
constexpr int DS  = 256;

// ---------------- scratch ----------------
__device__ float g_w      [(size_t)T * MEM];
__device__ float g_erase  [(size_t)T * DV];
__device__ float g_add    [(size_t)T * DV];
__device__ float g_reads  [(size_t)T * DV];
__device__ float g_summary[(size_t)T * DS];
__device__ float g_h      [(size_t)T * DS];
__device__ float g_d1     [(size_t)T * DK];

__device__ __forceinline__ float actf(float x, int a) {
    if (a == 1) return 1.f / (1.f + expf(-x));
    if (a == 2) return tanhf(x);
    return x;
}

// ---------------- attention logits + softmax (warp per token) ----------------
__global__ __launch_bounds__(256) void attn_kernel(
    const int* __restrict__ q_data,
    const float* __restrict__ q_table,
    const float* __restrict__ key_memory,
    float* __restrict__ w_out)
{
    __shared__ float ksm[32 * 129];
    int tid = threadIdx.x;
    for (int i = tid; i < 32 * 128; i += 256) {
        int m = i >> 7, k = i & 127;
        ksm[m * 129 + k] = key_memory[i];
    }
    __syncthreads();

    int warp = tid >> 5, lane = tid & 31;
    int t = blockIdx.x * 8 + warp;
    int row = q_data[t];

    float q0 = q_table[(size_t)row * 128 + lane];
    float q1 = q_table[(size_t)row * 128 + lane + 32];
    float q2 = q_table[(size_t)row * 128 + lane + 64];
    float q3 = q_table[(size_t)row * 128 + lane + 96];

    float lg = 0.f;
    #pragma unroll
    for (int k = 0; k < 128; ++k) {
        float qv;
        if (k < 32)       qv = __shfl_sync(0xffffffffu, q0, k & 31);
        else if (k < 64)  qv = __shfl_sync(0xffffffffu, q1, k & 31);
        else if (k < 96)  qv = __shfl_sync(0xffffffffu, q2, k & 31);
        else              qv = __shfl_sync(0xffffffffu, q3, k & 31);
        lg = fmaf(qv, ksm[lane * 129 + k], lg);
    }
    float mx = lg;
    #pragma unroll
    for (int off = 16; off > 0; off >>= 1)
        mx = fmaxf(mx, __shfl_xor_sync(0xffffffffu, mx, off));
    float e = expf(lg - mx);
    float sum = e;
    #pragma unroll
    for (int off = 16; off > 0; off >>= 1)
        sum += __shfl_xor_sync(0xffffffffu, sum, off);
    w_out[(size_t)t * 32 + lane] = e / sum;
}

// ---------------- bf16x3 tensor-core GEMM (warp-level mma.sync) ----------------
// CTA tile: M=128 tokens x N=128 cols. K in chunks of 64.
// out[t,n] = act( sum_k A[t,k]*W[k,n] + bias[n] ), A gathered by idx.
// grid.y picks (W, bias, act, out) group -> erase+add fuse into one launch.

constexpr int LDH = 72;                 // halves per smem row (64 data + 8 pad)
constexpr int TILE_H = 128 * LDH;       // halves per tile

__device__ __forceinline__ uint32_t pack_hi(float x, float y) {
    __nv_bfloat16 hx = __float2bfloat16(x);
    __nv_bfloat16 hy = __float2bfloat16(y);
    return ((uint32_t)__bfloat16_as_ushort(hy) << 16) | __bfloat16_as_ushort(hx);
}
__device__ __forceinline__ uint32_t pack_lo(float x, float y) {
    __nv_bfloat16 hx = __float2bfloat16(x);
    __nv_bfloat16 hy = __float2bfloat16(y);
    __nv_bfloat16 lx = __float2bfloat16(x - __bfloat162float(hx));
    __nv_bfloat16 ly = __float2bfloat16(y - __bfloat162float(hy));
    return ((uint32_t)__bfloat16_as_ushort(ly) << 16) | __bfloat16_as_ushort(lx);
}

__device__ __forceinline__ void mma16816(float* c, const uint32_t* a, const uint32_t* b) {
    asm volatile(
        "mma.sync.aligned.m16n8k16.row.col.f32.bf16.bf16.f32 "
        "{%0,%1,%2,%3}, {%4,%5,%6,%7}, {%8,%9}, {%0,%1,%2,%3};"
        : "+f"(c[0]), "+f"(c[1]), "+f"(c[2]), "+f"(c[3])
        : "r"(a[0]), "r"(a[1]), "r"(a[2]), "r"(a[3]), "r"(b[0]), "r"(b[1]));
}

__global__ __launch_bounds__(256, 2) void mma_gemm(
    const float* __restrict__ A0, const int* __restrict__ idx0, int ld0, int off0,
    const float* __restrict__ A1, const int* __restrict__ idx1, int ld1, int off1,
    int Ktot,
    const float* __restrict__ W0g, int ldW0, int wcol0, const float* __restrict__ bias0,
    int act0, float* __restrict__ out0, int ldo0, int ocol0,
    const float* __restrict__ W1g, int ldW1, int wcol1, const float* __restrict__ bias1,
    int act1, float* __restrict__ out1, int ldo1, int ocol1)
{
    extern __shared__ uint32_t smw[];   // word view of 4 tiles (each TILE_H/2 words)
    uint32_t* Ahw = smw;
    uint32_t* Alw = smw + TILE_H / 2;
    uint32_t* Bhw = smw + TILE_H;
    uint32_t* Blw = smw + 3 * (TILE_H / 2);

    int tid  = threadIdx.x;
    int wid  = tid >> 5, lane = tid & 31;
    int g    = lane >> 2, tq = lane & 3;
    int tok0 = blockIdx.x * 128;

    const float* W; int ldW, wcol, act, ldo, ocol; const float* bias; float* outp;
    if (blockIdx.y == 0) { W=W0g; ldW=ldW0; wcol=wcol0; bias=bias0; act=act0; outp=out0; ldo=ldo0; ocol=ocol0; }
    else                 { W=W1g; ldW=ldW1; wcol=wcol1; bias=bias1; act=act1; outp=out1; ldo=ldo1; ocol=ocol1; }

    int wm = (wid & 1) * 64;    // warp M offset (64 rows per warp)
    int wn = (wid >> 1) * 32;   // warp N offset (32 cols per warp)

    float acc[4][4][4];
    #pragma unroll
    for (int i = 0; i < 4; ++i)
        #pragma unroll
        for (int j = 0; j < 4; ++j)
            #pragma unroll
            for (int u = 0; u < 4; ++u) acc[i][j][u] = 0.f;

    int nch = Ktot >> 6;
    for (int c = 0; c < nch; ++c) {
        int kbase = c << 6;
        const float* Ab; const int* Ai; int Ald, Aoff;
        if (kbase < 128) { Ab = A0; Ai = idx0; Ald = ld0; Aoff = off0 + kbase; }
        else             { Ab = A1; Ai = idx1; Ald = ld1; Aoff = off1 + kbase - 128; }

        __syncthreads();   // previous chunk's compute done before overwrite

        // ---- A tile: 128 rows x 64 k, hi/lo. 4096 float2 loads / CTA ----
        #pragma unroll
        for (int j = 0; j < 16; ++j) {
            int e = tid + j * 256;
            int r = e >> 5, kp2 = e & 31;     // pair index 0..31 (k = 2*kp2)
            int t = tok0 + r;
            int gr = Ai ? Ai[t] : t;
            float2 v = *(const float2*)(Ab + (size_t)gr * Ald + Aoff + kp2 * 2);
            Ahw[r * 36 + kp2] = pack_hi(v.x, v.y);
            Alw[r * 36 + kp2] = pack_lo(v.x, v.y);
        }
        // ---- B tile: transpose W[k][n] -> smem[n][k], hi/lo, XOR swizzled ----
        #pragma unroll
        for (int j = 0; j < 16; ++j) {
            int e = tid + j * 256;
            int n = e & 127, kq = e >> 7;     // kq 0..31 (k = 2*kq)
            int kg = kbase + kq * 2;
            float v0 = W[(size_t)kg * ldW + wcol + n];
            float v1 = W[(size_t)(kg + 1) * ldW + wcol + n];
            int w = kq ^ (((n >> 3) & 3) << 2);
            Bhw[n * 36 + w] = pack_hi(v0, v1);
            Blw[n * 36 + w] = pack_lo(v0, v1);
        }
        __syncthreads();

        // ---- 3 passes: Ah*Bh, Ah*Bl, Al*Bh ----
        #pragma unroll
        for (int pass = 0; pass < 3; ++pass) {
            const uint32_t* Aw = (pass == 2) ? Alw : Ahw;
            const uint32_t* Bw = (pass == 1) ? Blw : Bhw;
            #pragma unroll
            for (int h = 0; h < 4; ++h) {      // four k16 steps in the 64-chunk
                uint32_t afr[4][4];
                #pragma unroll
                for (int mt = 0; mt < 4; ++mt) {
                    int base = (wm + mt * 16 + g) * 36 + h * 8 + tq;
                    afr[mt][0] = Aw[base];
                    afr[mt][1] = Aw[base + 288];       // +8 rows
                    afr[mt][2] = Aw[base + 4];         // +8 k halves
                    afr[mt][3] = Aw[base + 292];
                }
                uint32_t bfr[4][2];
                #pragma unroll
                for (int nt = 0; nt < 4; ++nt) {
                    int n  = wn + nt * 8 + g;
                    int sw = ((n >> 3) & 3) << 2;
                    int w0 = (h * 8 + tq) ^ sw;
                    bfr[nt][0] = Bw[n * 36 + w0];
                    bfr[nt][1] = Bw[n * 36 + (w0 ^ 4)];
                }
                #pragma unroll
                for (int mt = 0; mt < 4; ++mt)
                    #pragma unroll
                    for (int nt = 0; nt < 4; ++nt)
                        mma16816(acc[mt][nt], afr[mt], bfr[nt]);
            }
        }
    }

    // ---- epilogue: bias + activation + store ----
    #pragma unroll
    for (int nt = 0; nt < 4; ++nt) {
        int col = wn + nt * 8 + tq * 2;
        float2 bv = *(const float2*)(bias + col);
        #pragma unroll
        for (int mt = 0; mt < 4; ++mt) {
            int r0 = tok0 + wm + mt * 16 + g;
            float2 o0, o1;
            o0.x = actf(acc[mt][nt][0] + bv.x, act);
            o0.y = actf(acc[mt][nt][1] + bv.y, act);
            o1.x = actf(acc[mt][nt][2] + bv.x, act);
            o1.y = actf(acc[mt][nt][3] + bv.y, act);
            *(float2*)(outp + (size_t)r0 * ldo + ocol + col)       = o0;
            *(float2*)(outp + (size_t)(r0 + 8) * ldo + ocol + col) = o1;
        }
    }
}

// ---------------- DKVMN scan: block per batch, 256 threads (m-split), 4-step groups ----------------
__global__ __launch_bounds__(256) void scan_kernel(const float* __restrict__ ivm)
{
    int b   = blockIdx.x;
    int tid = threadIdx.x;
    int h   = tid >> 7;
    int d   = tid & 127;
    size_t tb = (size_t)b * S;

    float Mv[16];
    #pragma unroll
    for (int m = 0; m < 16; ++m)
        Mv[m] = ivm[(h * 16 + m) * 128 + d];

    __shared__ float wsm[2][4][32];
    __shared__ float rsm[2][4][128];

    float e[4], a[4];
    if (tid < 128)
        wsm[0][tid >> 5][tid & 31] = g_w[(tb + (tid >> 5)) * 32 + (tid & 31)];
    #pragma unroll
    for (int s = 0; s < 4; ++s) {
        e[s] = g_erase[(tb + s) * 128 + d];
        a[s] = g_add  [(tb + s) * 128 + d];
    }
    __syncthreads();

    for (int gg = 0; gg < S / 4; ++gg) {
        int cur = gg & 1, nxt = cur ^ 1;
        int sbase = gg * 4;
        float en[4], an[4];
        if (gg + 1 < S / 4) {
            if (tid < 128)
                wsm[nxt][tid >> 5][tid & 31] = g_w[(tb + sbase + 4 + (tid >> 5)) * 32 + (tid & 31)];
            #pragma unroll
            for (int s = 0; s < 4; ++s) {
                en[s] = g_erase[(tb + sbase + 4 + s) * 128 + d];
                an[s] = g_add  [(tb + sbase + 4 + s) * 128 + d];
            }
        } else {
            #pragma unroll
            for (int s = 0; s < 4; ++s) { en[s] = 0.f; an[s] = 0.f; }
        }

        float rloc[4];
        #pragma unroll
        for (int s = 0; s < 4; ++s) {
            float r = 0.f;
            #pragma unroll
            for (int m = 0; m < 16; ++m) {
                float wm = wsm[cur][s][h * 16 + m];
                r = fmaf(wm, Mv[m], r);                        // read BEFORE write
                Mv[m] = fmaf(wm, fmaf(-Mv[m], e[s], a[s]), Mv[m]);
            }
            if (h == 1) rsm[cur][s][d] = r;
            else        rloc[s] = r;
        }
        __syncthreads();
        if (h == 0) {
            #pragma unroll
            for (int s = 0; s < 4; ++s)
                g_reads[(tb + sbase + s) * 128 + d] = rloc[s] + rsm[cur][s][d];
        }
        #pragma unroll
        for (int s = 0; s < 4; ++s) { e[s] = en[s]; a[s] = an[s]; }
    }
}

// ---------------- final heads: warp per token ----------------
__global__ __launch_bounds__(128) void head_kernel(
    const float* __restrict__ W_ab2, const float* __restrict__ b_ab2,
    const float* __restrict__ W_df2, const float* __restrict__ b_df2,
    float* __restrict__ out)
{
    int warp = threadIdx.x >> 5, lane = threadIdx.x & 31;
    int t = blockIdx.x * 4 + warp;

    float pa = 0.f;
    #pragma unroll
    for (int j = 0; j < 8; ++j) {
        int k = lane + 32 * j;
        pa = fmaf(g_h[(size_t)t * 256 + k], W_ab2[k], pa);
    }
    float pd = 0.f;
    #pragma unroll
    for (int j = 0; j < 4; ++j) {
        int k = lane + 32 * j;
        pd = fmaf(g_d1[(size_t)t * 128 + k], W_df2[k], pd);
    }
    #pragma unroll
    for (int off = 16; off > 0; off >>= 1) {
        pa += __shfl_xor_sync(0xffffffffu, pa, off);
        pd += __shfl_xor_sync(0xffffffffu, pd, off);
    }
    if (lane == 0) {
        float ability    = pa + b_ab2[0];
        float difficulty = pd + b_df2[0];
        float z    = 3.0f * ability - difficulty;
        float pred = 1.f / (1.f + expf(-z));
        out[t]               = pred;
        out[(size_t)T + t]   = ability;
        out[(size_t)2*T + t] = difficulty;
        out[(size_t)3*T + t] = z;
    }
}

// ---------------- host launch ----------------
extern "C" void kernel_launch(void* const* d_in, const int* in_sizes, int n_in,
                              void* d_out, int out_size)
{
    const int*   q_data   = (const int*)  d_in[0];
    const int*   qa_data  = (const int*)  d_in[1];
    const float* q_table  = (const float*)d_in[2];
    const float* qa_table = (const float*)d_in[3];
    const float* key_mem  = (const float*)d_in[4];
    const float* init_vm  = (const float*)d_in[5];
    const float* W_erase  = (const float*)d_in[6];
    const float* b_erase  = (const float*)d_in[7];
    const float* W_add    = (const float*)d_in[8];
    const float* b_add    = (const float*)d_in[9];
    const float* W_sum    = (const float*)d_in[10];
    const float* b_sum    = (const float*)d_in[11];
    const float* W_ab1    = (const float*)d_in[12];
    const float* b_ab1    = (const float*)d_in[13];
    const float* W_ab2    = (const float*)d_in[14];
    const float* b_ab2    = (const float*)d_in[15];
    const float* W_df1    = (const float*)d_in[16];
    const float* b_df1    = (const float*)d_in[17];
    const float* W_df2    = (const float*)d_in[18];
    const float* b_df2    = (const float*)d_in[19];
    float* out = (float*)d_out;

    float *pw, *per, *pad, *prd, *psm, *ph, *pd1;
    cudaGetSymbolAddress((void**)&pw,  g_w);
    cudaGetSymbolAddress((void**)&per, g_erase);
    cudaGetSymbolAddress((void**)&pad, g_add);
    cudaGetSymbolAddress((void**)&prd, g_reads);
    cudaGetSymbolAddress((void**)&psm, g_summary);
    cudaGetSymbolAddress((void**)&ph,  g_h);
    cudaGetSymbolAddress((void**)&pd1, g_d1);

    constexpr int GSM = 2 * TILE_H * 4;   // 4 tiles x 128*72 halves x 2B = 73728 B
    cudaFuncSetAttribute(mma_gemm, cudaFuncAttributeMaxDynamicSharedMemorySize, GSM);

    const int MT = T / 128;   // 1024 M-tiles

    // 1. attention softmax weights
    attn_kernel<<<T / 8, 256>>>(q_data, q_table, key_mem, pw);

    // 2. erase (sigmoid) + add (tanh), fused: K=128, two N=128 groups
    mma_gemm<<<dim3(MT, 2), 256, GSM>>>(
        qa_table, qa_data, DV, 0,  nullptr, nullptr, 0, 0,  128,
        W_erase, 128, 0, b_erase, 1, per, 128, 0,
        W_add,   128, 0, b_add,   2, pad, 128, 0);

    // 3. difficulty hidden: tanh(qe @ W_df1 + b)
    mma_gemm<<<dim3(MT, 1), 256, GSM>>>(
        q_table, q_data, DK, 0,  nullptr, nullptr, 0, 0,  128,
        W_df1, 128, 0, b_df1, 2, pd1, 128, 0,
        W_df1, 128, 0, b_df1, 2, pd1, 128, 0);

    // 4. sequential DKVMN scan -> reads
    scan_kernel<<<B, 256>>>(init_vm);

    // 5. summary = tanh([reads | qe] @ W_sum + b), K=256, N=256 (two N-tiles)
    mma_gemm<<<dim3(MT, 2), 256, GSM>>>(
        prd, nullptr, DV, 0,  q_table, q_data, DK, 0,  256,
        W_sum, DS, 0,   b_sum,       2, psm, DS, 0,
        W_sum, DS, 128, b_sum + 128, 2, psm, DS, 128);

    // 6. ability hidden = tanh(summary @ W_ab1 + b), K=256, N=256
    mma_gemm<<<dim3(MT, 2), 256, GSM>>>(
        psm, nullptr, DS, 0,  psm, nullptr, DS, 128,  256,
        W_ab1, DS, 0,   b_ab1,       2, ph, DS, 0,
        W_ab1, DS, 128, b_ab1 + 128, 2, ph, DS, 128);

    // 7. heads
    head_kernel<<<T / 4, 128>>>(W_ab2, b_ab2, W_df2, b_df2, out);
}

// round 4
// speedup vs baseline: 1.6354x; 1.0115x over previous
#include <cuda_runtime.h>
#include <cuda_bf16.h>
#include <math.h>
#include <stdint.h>

constexpr int B   = 256;
constexpr int S   = 512;
constexpr int T   = B * S;       // 131072 tokens
constexpr int MEM = 32;
constexpr int DK  = 128;
constexpr int DV  = 128;
constexpr int DS  = 256;

// ---------------- scratch ----------------
__device__ float g_w    [(size_t)T * MEM];
__device__ float g_erase[(size_t)T * DV];
__device__ float g_add  [(size_t)T * DV];
__device__ float g_h    [(size_t)T * DS];
__device__ float g_d1   [(size_t)T * DK];

// bf16 hi/lo planes (split precision)
__device__ __nv_bfloat16 g_qe_h[(size_t)T * 128], g_qe_l[(size_t)T * 128];
__device__ __nv_bfloat16 g_qa_h[(size_t)T * 128], g_qa_l[(size_t)T * 128];
__device__ __nv_bfloat16 g_rd_h[(size_t)T * 128], g_rd_l[(size_t)T * 128];
__device__ __nv_bfloat16 g_sm_h[(size_t)T * 256], g_sm_l[(size_t)T * 256];

// transposed bf16 weights: Wt[n][k]
__device__ __nv_bfloat16 g_We_h[128*128], g_We_l[128*128];
__device__ __nv_bfloat16 g_Wa_h[128*128], g_Wa_l[128*128];
__device__ __nv_bfloat16 g_Wd_h[128*128], g_Wd_l[128*128];
__device__ __nv_bfloat16 g_Ws_h[256*256], g_Ws_l[256*256];
__device__ __nv_bfloat16 g_Wb_h[256*256], g_Wb_l[256*256];

__device__ __forceinline__ float actf(float x, int a) {
    if (a == 1) return 1.f / (1.f + expf(-x));
    if (a == 2) return tanhf(x);
    return x;
}
__device__ __forceinline__ uint32_t pack_hi(float x, float y) {
    __nv_bfloat16 hx = __float2bfloat16(x);
    __nv_bfloat16 hy = __float2bfloat16(y);
    return ((uint32_t)__bfloat16_as_ushort(hy) << 16) | __bfloat16_as_ushort(hx);
}
__device__ __forceinline__ uint32_t pack_lo(float x, float y) {
    __nv_bfloat16 hx = __float2bfloat16(x);
    __nv_bfloat16 hy = __float2bfloat16(y);
    __nv_bfloat16 lx = __float2bfloat16(x - __bfloat162float(hx));
    __nv_bfloat16 ly = __float2bfloat16(y - __bfloat162float(hy));
    return ((uint32_t)__bfloat16_as_ushort(ly) << 16) | __bfloat16_as_ushort(lx);
}

// ---------------- prep: gather + fp32 -> bf16 hi/lo ----------------
__global__ __launch_bounds__(256) void prep_gather(
    const int* __restrict__ q_data, const float* __restrict__ q_table,
    const int* __restrict__ qa_data, const float* __restrict__ qa_table)
{
    int t    = blockIdx.x * 8 + (threadIdx.x >> 5);
    int lane = threadIdx.x & 31;
    const int*   idx;
    const float* tab;
    __nv_bfloat16 *oh, *ol;
    if (blockIdx.y == 0) { idx = q_data;  tab = q_table;  oh = g_qe_h; ol = g_qe_l; }
    else                 { idx = qa_data; tab = qa_table; oh = g_qa_h; ol = g_qa_l; }
    int row = idx[t];
    float4 v = *(const float4*)(tab + (size_t)row * 128 + lane * 4);
    uint2 h, l;
    h.x = pack_hi(v.x, v.y); h.y = pack_hi(v.z, v.w);
    l.x = pack_lo(v.x, v.y); l.y = pack_lo(v.z, v.w);
    *(uint2*)(oh + (size_t)t * 128 + lane * 4) = h;
    *(uint2*)(ol + (size_t)t * 128 + lane * 4) = l;
}

// transpose+convert weight W[k][n] -> Wt[n][k] hi/lo
__global__ void prep_weight(const float* __restrict__ W, int K, int N,
                            __nv_bfloat16* __restrict__ th, __nv_bfloat16* __restrict__ tl)
{
    int e = blockIdx.x * 256 + threadIdx.x;
    if (e >= K * N) return;
    int k = e / N, n = e - k * N;
    float v = W[e];
    __nv_bfloat16 h = __float2bfloat16(v);
    th[(size_t)n * K + k] = h;
    tl[(size_t)n * K + k] = __float2bfloat16(v - __bfloat162float(h));
}

// ---------------- attention logits + softmax (warp per token) ----------------
__global__ __launch_bounds__(256) void attn_kernel(
    const int* __restrict__ q_data,
    const float* __restrict__ q_table,
    const float* __restrict__ key_memory,
    float* __restrict__ w_out)
{
    __shared__ float ksm[32 * 129];
    int tid = threadIdx.x;
    for (int i = tid; i < 32 * 128; i += 256) {
        int m = i >> 7, k = i & 127;
        ksm[m * 129 + k] = key_memory[i];
    }
    __syncthreads();

    int warp = tid >> 5, lane = tid & 31;
    int t = blockIdx.x * 8 + warp;
    int row = q_data[t];

    float q0 = q_table[(size_t)row * 128 + lane];
    float q1 = q_table[(size_t)row * 128 + lane + 32];
    float q2 = q_table[(size_t)row * 128 + lane + 64];
    float q3 = q_table[(size_t)row * 128 + lane + 96];

    float lg = 0.f;
    #pragma unroll
    for (int k = 0; k < 128; ++k) {
        float qv;
        if (k < 32)       qv = __shfl_sync(0xffffffffu, q0, k & 31);
        else if (k < 64)  qv = __shfl_sync(0xffffffffu, q1, k & 31);
        else if (k < 96)  qv = __shfl_sync(0xffffffffu, q2, k & 31);
        else              qv = __shfl_sync(0xffffffffu, q3, k & 31);
        lg = fmaf(qv, ksm[lane * 129 + k], lg);
    }
    float mx = lg;
    #pragma unroll
    for (int off = 16; off > 0; off >>= 1)
        mx = fmaxf(mx, __shfl_xor_sync(0xffffffffu, mx, off));
    float e = expf(lg - mx);
    float sum = e;
    #pragma unroll
    for (int off = 16; off > 0; off >>= 1)
        sum += __shfl_xor_sync(0xffffffffu, sum, off);
    w_out[(size_t)t * 32 + lane] = e / sum;
}

// ---------------- bf16x3 tensor-core GEMM ----------------
// CTA: M=128 tokens x N=128 cols, K chunks of 64. All operands pre-converted bf16.

struct GDesc {
    const __nv_bfloat16 *a0h, *a0l; int p0, o0;   // A chunk src for kbase < 128
    const __nv_bfloat16 *a1h, *a1l; int p1, o1;   // A chunk src for kbase >= 128
    const __nv_bfloat16 *wh, *wl;   int ldk, wcol;
    const float* bias;
    int act;        // 0 none, 1 sigmoid, 2 tanh
    int omode;      // 0 fp32, 1 bf16 hi/lo
    float* outf; int ldo, ocol;
    __nv_bfloat16 *oh, *ol; int ldob, ocolb;
};

__device__ __forceinline__ void mma16816(float* c, const uint32_t* a, const uint32_t* b) {
    asm volatile(
        "mma.sync.aligned.m16n8k16.row.col.f32.bf16.bf16.f32 "
        "{%0,%1,%2,%3}, {%4,%5,%6,%7}, {%8,%9}, {%0,%1,%2,%3};"
        : "+f"(c[0]), "+f"(c[1]), "+f"(c[2]), "+f"(c[3])
        : "r"(a[0]), "r"(a[1]), "r"(a[2]), "r"(a[3]), "r"(b[0]), "r"(b[1]));
}

constexpr int TILE_W = 128 * 36;   // words per tile (36-word padded rows)

__global__ __launch_bounds__(256, 2) void mma_gemm(int Ktot, GDesc G0, GDesc G1, GDesc G2)
{
    extern __shared__ uint32_t smw[];
    uint32_t* Ahw = smw;
    uint32_t* Alw = smw + TILE_W;
    uint32_t* Bhw = smw + 2 * TILE_W;
    uint32_t* Blw = smw + 3 * TILE_W;

    const GDesc G = (blockIdx.y == 0) ? G0 : ((blockIdx.y == 1) ? G1 : G2);

    int tid  = threadIdx.x;
    int wid  = tid >> 5, lane = tid & 31;
    int g    = lane >> 2, tq = lane & 3;
    int tok0 = blockIdx.x * 128;

    int wm = (wid & 1) * 64;
    int wn = (wid >> 1) * 32;

    float acc[4][4][4];
    #pragma unroll
    for (int i = 0; i < 4; ++i)
        #pragma unroll
        for (int j = 0; j < 4; ++j)
            #pragma unroll
            for (int u = 0; u < 4; ++u) acc[i][j][u] = 0.f;

    int nch = Ktot >> 6;
    for (int c = 0; c < nch; ++c) {
        int kbase = c << 6;
        const __nv_bfloat16 *Ah, *Al; int Ap, Ao;
        if (kbase < 128) { Ah = G.a0h; Al = G.a0l; Ap = G.p0; Ao = G.o0 + kbase; }
        else             { Ah = G.a1h; Al = G.a1l; Ap = G.p1; Ao = G.o1 + kbase - 128; }

        __syncthreads();

        // A tile: 128 rows x 64 halves, 16B granules. r = e>>3, q = e&7.
        #pragma unroll
        for (int j = 0; j < 4; ++j) {
            int e = tid + j * 256;
            int r = e >> 3, q = e & 7;
            size_t src = (size_t)(tok0 + r) * Ap + Ao + q * 8;
            *(uint4*)(Ahw + r * 36 + q * 4) = *(const uint4*)(Ah + src);
            *(uint4*)(Alw + r * 36 + q * 4) = *(const uint4*)(Al + src);
        }
        // B tile: Wt[wcol+n][kbase..], XOR swizzle at 4-word granularity
        #pragma unroll
        for (int j = 0; j < 4; ++j) {
            int e = tid + j * 256;
            int n = e >> 3, q = e & 7;
            size_t src = (size_t)(G.wcol + n) * G.ldk + kbase + q * 8;
            int sw = ((n >> 3) & 3) << 2;
            int dst = n * 36 + ((q * 4) ^ sw);
            *(uint4*)(Bhw + dst) = *(const uint4*)(G.wh + src);
            *(uint4*)(Blw + dst) = *(const uint4*)(G.wl + src);
        }
        __syncthreads();

        #pragma unroll
        for (int pass = 0; pass < 3; ++pass) {
            const uint32_t* Aw = (pass == 2) ? Alw : Ahw;
            const uint32_t* Bw = (pass == 1) ? Blw : Bhw;
            #pragma unroll
            for (int h = 0; h < 4; ++h) {
                uint32_t afr[4][4];
                #pragma unroll
                for (int mt = 0; mt < 4; ++mt) {
                    int base = (wm + mt * 16 + g) * 36 + h * 8 + tq;
                    afr[mt][0] = Aw[base];
                    afr[mt][1] = Aw[base + 288];
                    afr[mt][2] = Aw[base + 4];
                    afr[mt][3] = Aw[base + 292];
                }
                uint32_t bfr[4][2];
                #pragma unroll
                for (int nt = 0; nt < 4; ++nt) {
                    int n  = wn + nt * 8 + g;
                    int sw = ((n >> 3) & 3) << 2;
                    int w0 = (h * 8 + tq) ^ sw;
                    bfr[nt][0] = Bw[n * 36 + w0];
                    bfr[nt][1] = Bw[n * 36 + (w0 ^ 4)];
                }
                #pragma unroll
                for (int mt = 0; mt < 4; ++mt)
                    #pragma unroll
                    for (int nt = 0; nt < 4; ++nt)
                        mma16816(acc[mt][nt], afr[mt], bfr[nt]);
            }
        }
    }

    // epilogue
    #pragma unroll
    for (int nt = 0; nt < 4; ++nt) {
        int col = wn + nt * 8 + tq * 2;
        float2 bv = *(const float2*)(G.bias + col);
        #pragma unroll
        for (int mt = 0; mt < 4; ++mt) {
            int r0 = tok0 + wm + mt * 16 + g;
            float o00 = actf(acc[mt][nt][0] + bv.x, G.act);
            float o01 = actf(acc[mt][nt][1] + bv.y, G.act);
            float o10 = actf(acc[mt][nt][2] + bv.x, G.act);
            float o11 = actf(acc[mt][nt][3] + bv.y, G.act);
            if (G.omode == 0) {
                *(float2*)(G.outf + (size_t)r0 * G.ldo + G.ocol + col)       = make_float2(o00, o01);
                *(float2*)(G.outf + (size_t)(r0+8) * G.ldo + G.ocol + col)   = make_float2(o10, o11);
            } else {
                *(uint32_t*)(G.oh + (size_t)r0 * G.ldob + G.ocolb + col)     = pack_hi(o00, o01);
                *(uint32_t*)(G.ol + (size_t)r0 * G.ldob + G.ocolb + col)     = pack_lo(o00, o01);
                *(uint32_t*)(G.oh + (size_t)(r0+8) * G.ldob + G.ocolb + col) = pack_hi(o10, o11);
                *(uint32_t*)(G.ol + (size_t)(r0+8) * G.ldob + G.ocolb + col) = pack_lo(o10, o11);
            }
        }
    }
}

// ---------------- DKVMN scan: grid (B, 2 d-halves), 256 thr = 64 d x 4 m-quarters ----------------
__global__ __launch_bounds__(256) void scan_kernel(const float* __restrict__ ivm)
{
    int b   = blockIdx.x;
    int dh  = blockIdx.y * 64;
    int tid = threadIdx.x;
    int dl  = tid >> 2, mq = tid & 3;
    int d   = dh + dl;
    size_t tb = (size_t)b * S;

    float Mv[8];
    #pragma unroll
    for (int m = 0; m < 8; ++m)
        Mv[m] = ivm[(mq * 8 + m) * 128 + d];

    __shared__ float wsm[2][4][32];

    float e[4], a[4];
    if (tid < 128)
        wsm[0][tid >> 5][tid & 31] = g_w[(tb + (tid >> 5)) * 32 + (tid & 31)];
    #pragma unroll
    for (int s = 0; s < 4; ++s) {
        e[s] = g_erase[(tb + s) * 128 + d];
        a[s] = g_add  [(tb + s) * 128 + d];
    }
    __syncthreads();

    for (int gg = 0; gg < S / 4; ++gg) {
        int cur = gg & 1, nxt = cur ^ 1;
        int sbase = gg * 4;
        float en[4], an[4];
        if (gg + 1 < S / 4) {
            if (tid < 128)
                wsm[nxt][tid >> 5][tid & 31] = g_w[(tb + sbase + 4 + (tid >> 5)) * 32 + (tid & 31)];
            #pragma unroll
            for (int s = 0; s < 4; ++s) {
                en[s] = g_erase[(tb + sbase + 4 + s) * 128 + d];
                an[s] = g_add  [(tb + sbase + 4 + s) * 128 + d];
            }
        } else {
            #pragma unroll
            for (int s = 0; s < 4; ++s) { en[s] = 0.f; an[s] = 0.f; }
        }

        #pragma unroll
        for (int s = 0; s < 4; ++s) {
            float r = 0.f;
            #pragma unroll
            for (int m = 0; m < 8; ++m) {
                float wm = wsm[cur][s][mq * 8 + m];
                r = fmaf(wm, Mv[m], r);                        // read BEFORE write
                Mv[m] = fmaf(wm, fmaf(-Mv[m], e[s], a[s]), Mv[m]);
            }
            r += __shfl_xor_sync(0xffffffffu, r, 1);
            r += __shfl_xor_sync(0xffffffffu, r, 2);
            if (mq == 0) {
                __nv_bfloat16 h = __float2bfloat16(r);
                g_rd_h[(tb + sbase + s) * 128 + d] = h;
                g_rd_l[(tb + sbase + s) * 128 + d] = __float2bfloat16(r - __bfloat162float(h));
            }
        }
        __syncthreads();
        #pragma unroll
        for (int s = 0; s < 4; ++s) { e[s] = en[s]; a[s] = an[s]; }
    }
}

// ---------------- final heads: warp per token ----------------
__global__ __launch_bounds__(128) void head_kernel(
    const float* __restrict__ W_ab2, const float* __restrict__ b_ab2,
    const float* __restrict__ W_df2, const float* __restrict__ b_df2,
    float* __restrict__ out)
{
    int warp = threadIdx.x >> 5, lane = threadIdx.x & 31;
    int t = blockIdx.x * 4 + warp;

    float pa = 0.f;
    #pragma unroll
    for (int j = 0; j < 8; ++j) {
        int k = lane + 32 * j;
        pa = fmaf(g_h[(size_t)t * 256 + k], W_ab2[k], pa);
    }
    float pd = 0.f;
    #pragma unroll
    for (int j = 0; j < 4; ++j) {
        int k = lane + 32 * j;
        pd = fmaf(g_d1[(size_t)t * 128 + k], W_df2[k], pd);
    }
    #pragma unroll
    for (int off = 16; off > 0; off >>= 1) {
        pa += __shfl_xor_sync(0xffffffffu, pa, off);
        pd += __shfl_xor_sync(0xffffffffu, pd, off);
    }
    if (lane == 0) {
        float ability    = pa + b_ab2[0];
        float difficulty = pd + b_df2[0];
        float z    = 3.0f * ability - difficulty;
        float pred = 1.f / (1.f + expf(-z));
        out[t]               = pred;
        out[(size_t)T + t]   = ability;
        out[(size_t)2*T + t] = difficulty;
        out[(size_t)3*T + t] = z;
    }
}

// ---------------- host launch ----------------
extern "C" void kernel_launch(void* const* d_in, const int* in_sizes, int n_in,
                              void* d_out, int out_size)
{
    const int*   q_data   = (const int*)  d_in[0];
    const int*   qa_data  = (const int*)  d_in[1];
    const float* q_table  = (const float*)d_in[2];
    const float* qa_table = (const float*)d_in[3];
    const float* key_mem  = (const float*)d_in[4];
    const float* init_vm  = (const float*)d_in[5];
    const float* W_erase  = (const float*)d_in[6];
    const float* b_erase  = (const float*)d_in[7];
    const float* W_add    = (const float*)d_in[8];
    const float* b_add    = (const float*)d_in[9];
    const float* W_sum    = (const float*)d_in[10];
    const float* b_sum    = (const float*)d_in[11];
    const float* W_ab1    = (const float*)d_in[12];
    const float* b_ab1    = (const float*)d_in[13];
    const float* W_ab2    = (const float*)d_in[14];
    const float* b_ab2    = (const float*)d_in[15];
    const float* W_df1    = (const float*)d_in[16];
    const float* b_df1    = (const float*)d_in[17];
    const float* W_df2    = (const float*)d_in[18];
    const float* b_df2    = (const float*)d_in[19];
    float* out = (float*)d_out;

    // device pointers for __device__ symbols
    float *pw, *per, *pad, *ph, *pd1;
    __nv_bfloat16 *qeh, *qel, *qah, *qal, *rdh, *rdl, *smh, *sml;
    __nv_bfloat16 *Weh, *Wel, *Wah, *Wal, *Wdh, *Wdl, *Wsh, *Wsl, *Wbh, *Wbl;
    cudaGetSymbolAddress((void**)&pw,  g_w);
    cudaGetSymbolAddress((void**)&per, g_erase);
    cudaGetSymbolAddress((void**)&pad, g_add);
    cudaGetSymbolAddress((void**)&ph,  g_h);
    cudaGetSymbolAddress((void**)&pd1, g_d1);
    cudaGetSymbolAddress((void**)&qeh, g_qe_h); cudaGetSymbolAddress((void**)&qel, g_qe_l);
    cudaGetSymbolAddress((void**)&qah, g_qa_h); cudaGetSymbolAddress((void**)&qal, g_qa_l);
    cudaGetSymbolAddress((void**)&rdh, g_rd_h); cudaGetSymbolAddress((void**)&rdl, g_rd_l);
    cudaGetSymbolAddress((void**)&smh, g_sm_h); cudaGetSymbolAddress((void**)&sml, g_sm_l);
    cudaGetSymbolAddress((void**)&Weh, g_We_h); cudaGetSymbolAddress((void**)&Wel, g_We_l);
    cudaGetSymbolAddress((void**)&Wah, g_Wa_h); cudaGetSymbolAddress((void**)&Wal, g_Wa_l);
    cudaGetSymbolAddress((void**)&Wdh, g_Wd_h); cudaGetSymbolAddress((void**)&Wdl, g_Wd_l);
    cudaGetSymbolAddress((void**)&Wsh, g_Ws_h); cudaGetSymbolAddress((void**)&Wsl, g_Ws_l);
    cudaGetSymbolAddress((void**)&Wbh, g_Wb_h); cudaGetSymbolAddress((void**)&Wbl, g_Wb_l);

    constexpr int GSM = TILE_W * 4 * 4;   // 4 tiles x 4608 words x 4B = 73728 B
    cudaFuncSetAttribute(mma_gemm, cudaFuncAttributeMaxDynamicSharedMemorySize, GSM);

    const int MT = T / 128;

    // prep
    prep_gather<<<dim3(T / 8, 2), 256>>>(q_data, q_table, qa_data, qa_table);
    prep_weight<<<(128*128 + 255) / 256, 256>>>(W_erase, 128, 128, Weh, Wel);
    prep_weight<<<(128*128 + 255) / 256, 256>>>(W_add,   128, 128, Wah, Wal);
    prep_weight<<<(128*128 + 255) / 256, 256>>>(W_df1,   128, 128, Wdh, Wdl);
    prep_weight<<<(256*256 + 255) / 256, 256>>>(W_sum,   256, 256, Wsh, Wsl);
    prep_weight<<<(256*256 + 255) / 256, 256>>>(W_ab1,   256, 256, Wbh, Wbl);

    attn_kernel<<<T / 8, 256>>>(q_data, q_table, key_mem, pw);

    // erase / add / df1 fused (K=128)
    GDesc Ge = { qah, qal, 128, 0,  nullptr, nullptr, 0, 0,
                 Weh, Wel, 128, 0,  b_erase, 1, 0, per, 128, 0, nullptr, nullptr, 0, 0 };
    GDesc Ga = { qah, qal, 128, 0,  nullptr, nullptr, 0, 0,
                 Wah, Wal, 128, 0,  b_add,   2, 0, pad, 128, 0, nullptr, nullptr, 0, 0 };
    GDesc Gd = { qeh, qel, 128, 0,  nullptr, nullptr, 0, 0,
                 Wdh, Wdl, 128, 0,  b_df1,   2, 0, pd1, 128, 0, nullptr, nullptr, 0, 0 };
    mma_gemm<<<dim3(MT, 3), 256, GSM>>>(128, Ge, Ga, Gd);

    // scan
    scan_kernel<<<dim3(B, 2), 256>>>(init_vm);

    // summary = tanh([reads | qe] @ W_sum + b), K=256, out bf16 hi/lo
    GDesc Gs0 = { rdh, rdl, 128, 0,  qeh, qel, 128, 0,
                  Wsh, Wsl, 256, 0,    b_sum,       2, 1, nullptr, 0, 0, smh, sml, 256, 0 };
    GDesc Gs1 = { rdh, rdl, 128, 0,  qeh, qel, 128, 0,
                  Wsh, Wsl, 256, 128,  b_sum + 128, 2, 1, nullptr, 0, 0, smh, sml, 256, 128 };
    mma_gemm<<<dim3(MT, 2), 256, GSM>>>(256, Gs0, Gs1, Gs1);

    // ability hidden = tanh(summary @ W_ab1 + b), K=256, out fp32 g_h
    GDesc Gb0 = { smh, sml, 256, 0,  smh, sml, 256, 128,
                  Wbh, Wbl, 256, 0,    b_ab1,       2, 0, ph, 256, 0,   nullptr, nullptr, 0, 0 };
    GDesc Gb1 = { smh, sml, 256, 0,  smh, sml, 256, 128,
                  Wbh, Wbl, 256, 128,  b_ab1 + 128, 2, 0, ph, 256, 128, nullptr, nullptr, 0, 0 };
    mma_gemm<<<dim3(MT, 2), 256, GSM>>>(256, Gb0, Gb1, Gb1);

    // heads
    head_kernel<<<T / 4, 128>>>(W_ab2, b_ab2, W_df2, b_df2, out);
}

// round 5
// speedup vs baseline: 1.7608x; 1.0767x over previous
#include <cuda_runtime.h>
#include <cuda_bf16.h>
#include <math.h>
#include <stdint.h>

constexpr int B   = 256;
constexpr int S   = 512;
constexpr int T   = B * S;       // 131072 tokens
constexpr int MEM = 32;
constexpr int DK  = 128;
constexpr int DV  = 128;
constexpr int DS  = 256;

// ---------------- scratch ----------------
__device__ float g_w    [(size_t)T * MEM];
__device__ float g_erase[(size_t)T * DV];
__device__ float g_add  [(size_t)T * DV];
__device__ float g_h    [(size_t)T * DS];
__device__ float g_d1   [(size_t)T * DK];

__device__ __nv_bfloat16 g_qe_h[(size_t)T * 128], g_qe_l[(size_t)T * 128];
__device__ __nv_bfloat16 g_qa_h[(size_t)T * 128], g_qa_l[(size_t)T * 128];
__device__ __nv_bfloat16 g_rd_h[(size_t)T * 128], g_rd_l[(size_t)T * 128];
__device__ __nv_bfloat16 g_sm_h[(size_t)T * 256], g_sm_l[(size_t)T * 256];

__device__ __nv_bfloat16 g_We_h[128*128], g_We_l[128*128];
__device__ __nv_bfloat16 g_Wa_h[128*128], g_Wa_l[128*128];
__device__ __nv_bfloat16 g_Wd_h[128*128], g_Wd_l[128*128];
__device__ __nv_bfloat16 g_Ws_h[256*256], g_Ws_l[256*256];
__device__ __nv_bfloat16 g_Wb_h[256*256], g_Wb_l[256*256];

__device__ __forceinline__ float actf(float x, int a) {
    if (a == 1) return 1.f / (1.f + expf(-x));
    if (a == 2) return tanhf(x);
    return x;
}
__device__ __forceinline__ uint32_t pack_hi(float x, float y) {
    __nv_bfloat16 hx = __float2bfloat16(x);
    __nv_bfloat16 hy = __float2bfloat16(y);
    return ((uint32_t)__bfloat16_as_ushort(hy) << 16) | __bfloat16_as_ushort(hx);
}
__device__ __forceinline__ uint32_t pack_lo(float x, float y) {
    __nv_bfloat16 hx = __float2bfloat16(x);
    __nv_bfloat16 hy = __float2bfloat16(y);
    __nv_bfloat16 lx = __float2bfloat16(x - __bfloat162float(hx));
    __nv_bfloat16 ly = __float2bfloat16(y - __bfloat162float(hy));
    return ((uint32_t)__bfloat16_as_ushort(ly) << 16) | __bfloat16_as_ushort(lx);
}

// ---------------- prep: all 5 weights, one launch ----------------
__global__ __launch_bounds__(256) void prep_weight_all(
    const float* __restrict__ W0, const float* __restrict__ W1,
    const float* __restrict__ W2, const float* __restrict__ W3,
    const float* __restrict__ W4)
{
    int bid = blockIdx.x;
    const float* W; __nv_bfloat16 *th, *tl; int K, N, base;
    if (bid < 64)       { W = W0; th = g_We_h; tl = g_We_l; K = 128; N = 128; base = 0; }
    else if (bid < 128) { W = W1; th = g_Wa_h; tl = g_Wa_l; K = 128; N = 128; base = 64; }
    else if (bid < 192) { W = W2; th = g_Wd_h; tl = g_Wd_l; K = 128; N = 128; base = 128; }
    else if (bid < 448) { W = W3; th = g_Ws_h; tl = g_Ws_l; K = 256; N = 256; base = 192; }
    else                { W = W4; th = g_Wb_h; tl = g_Wb_l; K = 256; N = 256; base = 448; }
    int e = (bid - base) * 256 + threadIdx.x;
    int k = e / N, n = e - k * N;
    float v = W[e];
    __nv_bfloat16 h = __float2bfloat16(v);
    th[(size_t)n * K + k] = h;
    tl[(size_t)n * K + k] = __float2bfloat16(v - __bfloat162float(h));
}

// ---------------- prep: gather + fp32 -> bf16 hi/lo ----------------
__global__ __launch_bounds__(256) void prep_gather(
    const int* __restrict__ q_data, const float* __restrict__ q_table,
    const int* __restrict__ qa_data, const float* __restrict__ qa_table)
{
    int t    = blockIdx.x * 8 + (threadIdx.x >> 5);
    int lane = threadIdx.x & 31;
    const int*   idx;
    const float* tab;
    __nv_bfloat16 *oh, *ol;
    if (blockIdx.y == 0) { idx = q_data;  tab = q_table;  oh = g_qe_h; ol = g_qe_l; }
    else                 { idx = qa_data; tab = qa_table; oh = g_qa_h; ol = g_qa_l; }
    int row = idx[t];
    float4 v = *(const float4*)(tab + (size_t)row * 128 + lane * 4);
    uint2 h, l;
    h.x = pack_hi(v.x, v.y); h.y = pack_hi(v.z, v.w);
    l.x = pack_lo(v.x, v.y); l.y = pack_lo(v.z, v.w);
    *(uint2*)(oh + (size_t)t * 128 + lane * 4) = h;
    *(uint2*)(ol + (size_t)t * 128 + lane * 4) = l;
}

// ---------------- attention logits + softmax ----------------
__global__ __launch_bounds__(256) void attn_kernel(
    const int* __restrict__ q_data,
    const float* __restrict__ q_table,
    const float* __restrict__ key_memory,
    float* __restrict__ w_out)
{
    __shared__ float ksm[32 * 129];
    int tid = threadIdx.x;
    for (int i = tid; i < 32 * 128; i += 256) {
        int m = i >> 7, k = i & 127;
        ksm[m * 129 + k] = key_memory[i];
    }
    __syncthreads();

    int warp = tid >> 5, lane = tid & 31;
    int t = blockIdx.x * 8 + warp;
    int row = q_data[t];

    float q0 = q_table[(size_t)row * 128 + lane];
    float q1 = q_table[(size_t)row * 128 + lane + 32];
    float q2 = q_table[(size_t)row * 128 + lane + 64];
    float q3 = q_table[(size_t)row * 128 + lane + 96];

    float lg = 0.f;
    #pragma unroll
    for (int k = 0; k < 128; ++k) {
        float qv;
        if (k < 32)       qv = __shfl_sync(0xffffffffu, q0, k & 31);
        else if (k < 64)  qv = __shfl_sync(0xffffffffu, q1, k & 31);
        else if (k < 96)  qv = __shfl_sync(0xffffffffu, q2, k & 31);
        else              qv = __shfl_sync(0xffffffffu, q3, k & 31);
        lg = fmaf(qv, ksm[lane * 129 + k], lg);
    }
    float mx = lg;
    #pragma unroll
    for (int off = 16; off > 0; off >>= 1)
        mx = fmaxf(mx, __shfl_xor_sync(0xffffffffu, mx, off));
    float e = expf(lg - mx);
    float sum = e;
    #pragma unroll
    for (int off = 16; off > 0; off >>= 1)
        sum += __shfl_xor_sync(0xffffffffu, sum, off);
    w_out[(size_t)t * 32 + lane] = e / sum;
}

// ---------------- bf16x3 tensor-core GEMM, cp.async double-buffered + ldmatrix ----------------
struct GDesc {
    const __nv_bfloat16 *a0h, *a0l; int p0, o0;
    const __nv_bfloat16 *a1h, *a1l; int p1, o1;
    const __nv_bfloat16 *wh, *wl;   int ldk, wcol;
    const float* bias;
    int act;
    int omode;      // 0 fp32, 1 bf16 hi/lo
    float* outf; int ldo, ocol;
    __nv_bfloat16 *oh, *ol; int ldob, ocolb;
};

__device__ __forceinline__ void mma16816(float* c, const uint32_t* a, const uint32_t* b) {
    asm volatile(
        "mma.sync.aligned.m16n8k16.row.col.f32.bf16.bf16.f32 "
        "{%0,%1,%2,%3}, {%4,%5,%6,%7}, {%8,%9}, {%0,%1,%2,%3};"
        : "+f"(c[0]), "+f"(c[1]), "+f"(c[2]), "+f"(c[3])
        : "r"(a[0]), "r"(a[1]), "r"(a[2]), "r"(a[3]), "r"(b[0]), "r"(b[1]));
}
#define LDSM4(r, addr) \
    asm volatile("ldmatrix.sync.aligned.m8n8.x4.shared.b16 {%0,%1,%2,%3}, [%4];" \
        : "=r"((r)[0]), "=r"((r)[1]), "=r"((r)[2]), "=r"((r)[3]) : "r"(addr))

__device__ __forceinline__ void cpa16(uint32_t dst, const void* src) {
    asm volatile("cp.async.cg.shared.global [%0], [%1], 16;" :: "r"(dst), "l"(src));
}

constexpr int TW  = 128 * 36;      // words per tile (36-word padded rows)
constexpr int TWB = TW * 4;        // tile bytes = 18432

__device__ __forceinline__ void prefetch_chunk(const GDesc& G, int tok0, int kbase,
                                               uint32_t stbase, int tid)
{
    const __nv_bfloat16 *Ah, *Al; int Ap, Ao;
    if (kbase < 128) { Ah = G.a0h; Al = G.a0l; Ap = G.p0; Ao = G.o0 + kbase; }
    else             { Ah = G.a1h; Al = G.a1l; Ap = G.p1; Ao = G.o1 + kbase - 128; }
    #pragma unroll
    for (int j = 0; j < 4; ++j) {
        int e = tid + j * 256;
        int r = e >> 3, q = e & 7;
        size_t src = (size_t)(tok0 + r) * Ap + Ao + q * 8;
        uint32_t dst = stbase + (uint32_t)(r * 36 + q * 4) * 4;
        cpa16(dst,       Ah + src);
        cpa16(dst + TWB, Al + src);
    }
    #pragma unroll
    for (int j = 0; j < 4; ++j) {
        int e = tid + j * 256;
        int n = e >> 3, q = e & 7;
        size_t src = (size_t)(G.wcol + n) * G.ldk + kbase + q * 8;
        uint32_t dst = stbase + 2u * TWB + (uint32_t)(n * 36 + q * 4) * 4;
        cpa16(dst,       G.wh + src);
        cpa16(dst + TWB, G.wl + src);
    }
}

__global__ __launch_bounds__(256) void mma_gemm(int Ktot, GDesc G0, GDesc G1, GDesc G2)
{
    extern __shared__ __align__(16) uint32_t smw[];
    uint32_t sbase = (uint32_t)__cvta_generic_to_shared(smw);

    const GDesc G = (blockIdx.y == 0) ? G0 : ((blockIdx.y == 1) ? G1 : G2);

    int tid  = threadIdx.x;
    int wid  = tid >> 5, lane = tid & 31;
    int g    = lane >> 2, tq = lane & 3;
    int tok0 = blockIdx.x * 128;

    int wm = (wid & 1) * 64;
    int wn = (wid >> 1) * 32;

    // lane-dependent ldmatrix offsets (bytes)
    uint32_t arow = (uint32_t)(((lane & 15) * 36 + (lane >> 4) * 4) * 4);
    int jb = lane >> 3;
    uint32_t brow = (uint32_t)(((((jb >> 1) * 8) + (lane & 7)) * 36 + (jb & 1) * 4) * 4);

    float acc[4][4][4];
    #pragma unroll
    for (int i = 0; i < 4; ++i)
        #pragma unroll
        for (int j = 0; j < 4; ++j)
            #pragma unroll
            for (int u = 0; u < 4; ++u) acc[i][j][u] = 0.f;

    int nch = Ktot >> 6;

    prefetch_chunk(G, tok0, 0, sbase, tid);
    asm volatile("cp.async.commit_group;");

    for (int c = 0; c < nch; ++c) {
        if (c + 1 < nch) {
            prefetch_chunk(G, tok0, (c + 1) << 6, sbase + (uint32_t)((c + 1) & 1) * 4u * TWB, tid);
            asm volatile("cp.async.commit_group;");
            asm volatile("cp.async.wait_group 1;");
        } else {
            asm volatile("cp.async.wait_group 0;");
        }
        __syncthreads();

        uint32_t Ab = sbase + (uint32_t)(c & 1) * 4u * TWB;
        uint32_t Bb = Ab + 2u * TWB;

        #pragma unroll
        for (int h = 0; h < 4; ++h) {
            uint32_t ah[4][4], al[4][4], bh[2][4], bl[2][4];
            #pragma unroll
            for (int mt = 0; mt < 4; ++mt) {
                uint32_t addr = Ab + (uint32_t)((wm + mt * 16) * 144) + arow + (uint32_t)(h * 32);
                LDSM4(ah[mt], addr);
                LDSM4(al[mt], addr + TWB);
            }
            #pragma unroll
            for (int ntp = 0; ntp < 2; ++ntp) {
                uint32_t addr = Bb + (uint32_t)((wn + ntp * 16) * 144) + brow + (uint32_t)(h * 32);
                LDSM4(bh[ntp], addr);
                LDSM4(bl[ntp], addr + TWB);
            }
            #pragma unroll
            for (int mt = 0; mt < 4; ++mt)
                #pragma unroll
                for (int nt = 0; nt < 4; ++nt)
                    mma16816(acc[mt][nt], ah[mt], &bh[nt >> 1][(nt & 1) * 2]);
            #pragma unroll
            for (int mt = 0; mt < 4; ++mt)
                #pragma unroll
                for (int nt = 0; nt < 4; ++nt)
                    mma16816(acc[mt][nt], ah[mt], &bl[nt >> 1][(nt & 1) * 2]);
            #pragma unroll
            for (int mt = 0; mt < 4; ++mt)
                #pragma unroll
                for (int nt = 0; nt < 4; ++nt)
                    mma16816(acc[mt][nt], al[mt], &bh[nt >> 1][(nt & 1) * 2]);
        }
        __syncthreads();
    }

    // epilogue
    #pragma unroll
    for (int nt = 0; nt < 4; ++nt) {
        int col = wn + nt * 8 + tq * 2;
        float2 bv = *(const float2*)(G.bias + col);
        #pragma unroll
        for (int mt = 0; mt < 4; ++mt) {
            int r0 = tok0 + wm + mt * 16 + g;
            float o00 = actf(acc[mt][nt][0] + bv.x, G.act);
            float o01 = actf(acc[mt][nt][1] + bv.y, G.act);
            float o10 = actf(acc[mt][nt][2] + bv.x, G.act);
            float o11 = actf(acc[mt][nt][3] + bv.y, G.act);
            if (G.omode == 0) {
                *(float2*)(G.outf + (size_t)r0 * G.ldo + G.ocol + col)     = make_float2(o00, o01);
                *(float2*)(G.outf + (size_t)(r0+8) * G.ldo + G.ocol + col) = make_float2(o10, o11);
            } else {
                *(uint32_t*)(G.oh + (size_t)r0 * G.ldob + G.ocolb + col)     = pack_hi(o00, o01);
                *(uint32_t*)(G.ol + (size_t)r0 * G.ldob + G.ocolb + col)     = pack_lo(o00, o01);
                *(uint32_t*)(G.oh + (size_t)(r0+8) * G.ldob + G.ocolb + col) = pack_hi(o10, o11);
                *(uint32_t*)(G.ol + (size_t)(r0+8) * G.ldob + G.ocolb + col) = pack_lo(o10, o11);
            }
        }
    }
}

// ---------------- DKVMN scan ----------------
__global__ __launch_bounds__(256) void scan_kernel(const float* __restrict__ ivm)
{
    int b   = blockIdx.x;
    int dh  = blockIdx.y * 64;
    int tid = threadIdx.x;
    int dl  = tid >> 2, mq = tid & 3;
    int d   = dh + dl;
    size_t tb = (size_t)b * S;

    float Mv[8];
    #pragma unroll
    for (int m = 0; m < 8; ++m)
        Mv[m] = ivm[(mq * 8 + m) * 128 + d];

    __shared__ float wsm[2][4][32];

    float e[4], a[4];
    if (tid < 128)
        wsm[0][tid >> 5][tid & 31] = g_w[(tb + (tid >> 5)) * 32 + (tid & 31)];
    #pragma unroll
    for (int s = 0; s < 4; ++s) {
        e[s] = g_erase[(tb + s) * 128 + d];
        a[s] = g_add  [(tb + s) * 128 + d];
    }
    __syncthreads();

    for (int gg = 0; gg < S / 4; ++gg) {
        int cur = gg & 1, nxt = cur ^ 1;
        int sbase = gg * 4;
        float en[4], an[4];
        if (gg + 1 < S / 4) {
            if (tid < 128)
                wsm[nxt][tid >> 5][tid & 31] = g_w[(tb + sbase + 4 + (tid >> 5)) * 32 + (tid & 31)];
            #pragma unroll
            for (int s = 0; s < 4; ++s) {
                en[s] = g_erase[(tb + sbase + 4 + s) * 128 + d];
                an[s] = g_add  [(tb + sbase + 4 + s) * 128 + d];
            }
        } else {
            #pragma unroll
            for (int s = 0; s < 4; ++s) { en[s] = 0.f; an[s] = 0.f; }
        }

        #pragma unroll
        for (int s = 0; s < 4; ++s) {
            float r = 0.f;
            #pragma unroll
            for (int m = 0; m < 8; ++m) {
                float wm = wsm[cur][s][mq * 8 + m];
                r = fmaf(wm, Mv[m], r);                        // read BEFORE write
                Mv[m] = fmaf(wm, fmaf(-Mv[m], e[s], a[s]), Mv[m]);
            }
            r += __shfl_xor_sync(0xffffffffu, r, 1);
            r += __shfl_xor_sync(0xffffffffu, r, 2);
            if (mq == 0) {
                __nv_bfloat16 h = __float2bfloat16(r);
                g_rd_h[(tb + sbase + s) * 128 + d] = h;
                g_rd_l[(tb + sbase + s) * 128 + d] = __float2bfloat16(r - __bfloat162float(h));
            }
        }
        __syncthreads();
        #pragma unroll
        for (int s = 0; s < 4; ++s) { e[s] = en[s]; a[s] = an[s]; }
    }
}

// ---------------- final heads ----------------
__global__ __launch_bounds__(128) void head_kernel(
    const float* __restrict__ W_ab2, const float* __restrict__ b_ab2,
    const float* __restrict__ W_df2, const float* __restrict__ b_df2,
    float* __restrict__ out)
{
    int warp = threadIdx.x >> 5, lane = threadIdx.x & 31;
    int t = blockIdx.x * 4 + warp;

    float pa = 0.f;
    #pragma unroll
    for (int j = 0; j < 8; ++j) {
        int k = lane + 32 * j;
        pa = fmaf(g_h[(size_t)t * 256 + k], W_ab2[k], pa);
    }
    float pd = 0.f;
    #pragma unroll
    for (int j = 0; j < 4; ++j) {
        int k = lane + 32 * j;
        pd = fmaf(g_d1[(size_t)t * 128 + k], W_df2[k], pd);
    }
    #pragma unroll
    for (int off = 16; off > 0; off >>= 1) {
        pa += __shfl_xor_sync(0xffffffffu, pa, off);
        pd += __shfl_xor_sync(0xffffffffu, pd, off);
    }
    if (lane == 0) {
        float ability    = pa + b_ab2[0];
        float difficulty = pd + b_df2[0];
        float z    = 3.0f * ability - difficulty;
        float pred = 1.f / (1.f + expf(-z));
        out[t]               = pred;
        out[(size_t)T + t]   = ability;
        out[(size_t)2*T + t] = difficulty;
        out[(size_t)3*T + t] = z;
    }
}

// ---------------- host launch ----------------
extern "C" void kernel_launch(void* const* d_in, const int* in_sizes, int n_in,
                              void* d_out, int out_size)
{
    const int*   q_data   = (const int*)  d_in[0];
    const int*   qa_data  = (const int*)  d_in[1];
    const float* q_table  = (const float*)d_in[2];
    const float* qa_table = (const float*)d_in[3];
    const float* key_mem  = (const float*)d_in[4];
    const float* init_vm  = (const float*)d_in[5];
    const float* W_erase  = (const float*)d_in[6];
    const float* b_erase  = (const float*)d_in[7];
    const float* W_add    = (const float*)d_in[8];
    const float* b_add    = (const float*)d_in[9];
    const float* W_sum    = (const float*)d_in[10];
    const float* b_sum    = (const float*)d_in[11];
    const float* W_ab1    = (const float*)d_in[12];
    const float* b_ab1    = (const float*)d_in[13];
    const float* W_ab2    = (const float*)d_in[14];
    const float* b_ab2    = (const float*)d_in[15];
    const float* W_df1    = (const float*)d_in[16];
    const float* b_df1    = (const float*)d_in[17];
    const float* W_df2    = (const float*)d_in[18];
    const float* b_df2    = (const float*)d_in[19];
    float* out = (float*)d_out;

    float *pw, *per, *pad, *ph, *pd1;
    __nv_bfloat16 *qeh, *qel, *qah, *qal, *rdh, *rdl, *smh, *sml;
    __nv_bfloat16 *Weh, *Wel, *Wah, *Wal, *Wdh, *Wdl, *Wsh, *Wsl, *Wbh, *Wbl;
    cudaGetSymbolAddress((void**)&pw,  g_w);
    cudaGetSymbolAddress((void**)&per, g_erase);
    cudaGetSymbolAddress((void**)&pad, g_add);
    cudaGetSymbolAddress((void**)&ph,  g_h);
    cudaGetSymbolAddress((void**)&pd1, g_d1);
    cudaGetSymbolAddress((void**)&qeh, g_qe_h); cudaGetSymbolAddress((void**)&qel, g_qe_l);
    cudaGetSymbolAddress((void**)&qah, g_qa_h); cudaGetSymbolAddress((void**)&qal, g_qa_l);
    cudaGetSymbolAddress((void**)&rdh, g_rd_h); cudaGetSymbolAddress((void**)&rdl, g_rd_l);
    cudaGetSymbolAddress((void**)&smh, g_sm_h); cudaGetSymbolAddress((void**)&sml, g_sm_l);
    cudaGetSymbolAddress((void**)&Weh, g_We_h); cudaGetSymbolAddress((void**)&Wel, g_We_l);
    cudaGetSymbolAddress((void**)&Wah, g_Wa_h); cudaGetSymbolAddress((void**)&Wal, g_Wa_l);
    cudaGetSymbolAddress((void**)&Wdh, g_Wd_h); cudaGetSymbolAddress((void**)&Wdl, g_Wd_l);
    cudaGetSymbolAddress((void**)&Wsh, g_Ws_h); cudaGetSymbolAddress((void**)&Wsl, g_Ws_l);
    cudaGetSymbolAddress((void**)&Wbh, g_Wb_h); cudaGetSymbolAddress((void**)&Wbl, g_Wb_l);

    constexpr int GSM = 2 * 4 * TWB;   // 147456 B, double-buffered
    cudaFuncSetAttribute(mma_gemm, cudaFuncAttributeMaxDynamicSharedMemorySize, GSM);

    const int MT = T / 128;

    // [1] weights prep (fused), [2] gather prep, [3] attn
    prep_weight_all<<<704, 256>>>(W_erase, W_add, W_df1, W_sum, W_ab1);
    prep_gather<<<dim3(T / 8, 2), 256>>>(q_data, q_table, qa_data, qa_table);
    attn_kernel<<<T / 8, 256>>>(q_data, q_table, key_mem, pw);

    // [4] erase / add / df1 fused (K=128)
    GDesc Ge = { qah, qal, 128, 0,  nullptr, nullptr, 0, 0,
                 Weh, Wel, 128, 0,  b_erase, 1, 0, per, 128, 0, nullptr, nullptr, 0, 0 };
    GDesc Ga = { qah, qal, 128, 0,  nullptr, nullptr, 0, 0,
                 Wah, Wal, 128, 0,  b_add,   2, 0, pad, 128, 0, nullptr, nullptr, 0, 0 };
    GDesc Gd = { qeh, qel, 128, 0,  nullptr, nullptr, 0, 0,
                 Wdh, Wdl, 128, 0,  b_df1,   2, 0, pd1, 128, 0, nullptr, nullptr, 0, 0 };
    mma_gemm<<<dim3(MT, 3), 256, GSM>>>(128, Ge, Ga, Gd);

    // [5] scan
    scan_kernel<<<dim3(B, 2), 256>>>(init_vm);

    // [6] summary = tanh([reads | qe] @ W_sum + b), K=256  (this is the profiled launch)
    GDesc Gs0 = { rdh, rdl, 128, 0,  qeh, qel, 128, 0,
                  Wsh, Wsl, 256, 0,    b_sum,       2, 1, nullptr, 0, 0, smh, sml, 256, 0 };
    GDesc Gs1 = { rdh, rdl, 128, 0,  qeh, qel, 128, 0,
                  Wsh, Wsl, 256, 128,  b_sum + 128, 2, 1, nullptr, 0, 0, smh, sml, 256, 128 };
    mma_gemm<<<dim3(MT, 2), 256, GSM>>>(256, Gs0, Gs1, Gs1);

    // [7] ability hidden = tanh(summary @ W_ab1 + b), K=256
    GDesc Gb0 = { smh, sml, 256, 0,  smh, sml, 256, 128,
                  Wbh, Wbl, 256, 0,    b_ab1,       2, 0, ph, 256, 0,   nullptr, nullptr, 0, 0 };
    GDesc Gb1 = { smh, sml, 256, 0,  smh, sml, 256, 128,
                  Wbh, Wbl, 256, 128,  b_ab1 + 128, 2, 0, ph, 256, 128, nullptr, nullptr, 0, 0 };
    mma_gemm<<<dim3(MT, 2), 256, GSM>>>(256, Gb0, Gb1, Gb1);

    // [8] heads
    head_kernel<<<T / 4, 128>>>(W_ab2, b_ab2, W_df2, b_df2, out);
}

// round 6
// speedup vs baseline: 1.9282x; 1.0951x over previous
#include <cuda_runtime.h>
#include <cuda_bf16.h>
#include <math.h>
#include <stdint.h>

constexpr int B   = 256;
constexpr int S   = 512;
constexpr int T   = B * S;       // 131072 tokens
constexpr int MEM = 32;
constexpr int DK  = 128;
constexpr int DV  = 128;
constexpr int DS  = 256;

// ---------------- scratch ----------------
__device__ float g_w    [(size_t)T * MEM];
__device__ float g_erase[(size_t)T * DV];
__device__ float g_add  [(size_t)T * DV];
__device__ float g_h    [(size_t)T * DS];
__device__ float g_d1   [(size_t)T * DK];

__device__ __nv_bfloat16 g_qe_h[(size_t)T * 128], g_qe_l[(size_t)T * 128];
__device__ __nv_bfloat16 g_qa_h[(size_t)T * 128], g_qa_l[(size_t)T * 128];
__device__ __nv_bfloat16 g_rd_h[(size_t)T * 128], g_rd_l[(size_t)T * 128];
__device__ __nv_bfloat16 g_sm_h[(size_t)T * 256], g_sm_l[(size_t)T * 256];

__device__ __nv_bfloat16 g_We_h[128*128], g_We_l[128*128];
__device__ __nv_bfloat16 g_Wa_h[128*128], g_Wa_l[128*128];
__device__ __nv_bfloat16 g_Wd_h[128*128], g_Wd_l[128*128];
__device__ __nv_bfloat16 g_Ws_h[256*256], g_Ws_l[256*256];
__device__ __nv_bfloat16 g_Wb_h[256*256], g_Wb_l[256*256];

__device__ __forceinline__ float actf(float x, int a) {
    if (a == 1) return 1.f / (1.f + expf(-x));
    if (a == 2) return tanhf(x);
    return x;
}
__device__ __forceinline__ uint32_t pack_hi(float x, float y) {
    __nv_bfloat16 hx = __float2bfloat16(x);
    __nv_bfloat16 hy = __float2bfloat16(y);
    return ((uint32_t)__bfloat16_as_ushort(hy) << 16) | __bfloat16_as_ushort(hx);
}
__device__ __forceinline__ uint32_t pack_lo(float x, float y) {
    __nv_bfloat16 hx = __float2bfloat16(x);
    __nv_bfloat16 hy = __float2bfloat16(y);
    __nv_bfloat16 lx = __float2bfloat16(x - __bfloat162float(hx));
    __nv_bfloat16 ly = __float2bfloat16(y - __bfloat162float(hy));
    return ((uint32_t)__bfloat16_as_ushort(ly) << 16) | __bfloat16_as_ushort(lx);
}

// ---------------- prep: all 5 weights, one launch ----------------
__global__ __launch_bounds__(256) void prep_weight_all(
    const float* __restrict__ W0, const float* __restrict__ W1,
    const float* __restrict__ W2, const float* __restrict__ W3,
    const float* __restrict__ W4)
{
    int bid = blockIdx.x;
    const float* W; __nv_bfloat16 *th, *tl; int K, N, base;
    if (bid < 64)       { W = W0; th = g_We_h; tl = g_We_l; K = 128; N = 128; base = 0; }
    else if (bid < 128) { W = W1; th = g_Wa_h; tl = g_Wa_l; K = 128; N = 128; base = 64; }
    else if (bid < 192) { W = W2; th = g_Wd_h; tl = g_Wd_l; K = 128; N = 128; base = 128; }
    else if (bid < 448) { W = W3; th = g_Ws_h; tl = g_Ws_l; K = 256; N = 256; base = 192; }
    else                { W = W4; th = g_Wb_h; tl = g_Wb_l; K = 256; N = 256; base = 448; }
    int e = (bid - base) * 256 + threadIdx.x;
    int k = e / N, n = e - k * N;
    float v = W[e];
    __nv_bfloat16 h = __float2bfloat16(v);
    th[(size_t)n * K + k] = h;
    tl[(size_t)n * K + k] = __float2bfloat16(v - __bfloat162float(h));
}

// ---------------- prep: gather + fp32 -> bf16 hi/lo ----------------
__global__ __launch_bounds__(256) void prep_gather(
    const int* __restrict__ q_data, const float* __restrict__ q_table,
    const int* __restrict__ qa_data, const float* __restrict__ qa_table)
{
    int t    = blockIdx.x * 8 + (threadIdx.x >> 5);
    int lane = threadIdx.x & 31;
    const int*   idx;
    const float* tab;
    __nv_bfloat16 *oh, *ol;
    if (blockIdx.y == 0) { idx = q_data;  tab = q_table;  oh = g_qe_h; ol = g_qe_l; }
    else                 { idx = qa_data; tab = qa_table; oh = g_qa_h; ol = g_qa_l; }
    int row = idx[t];
    float4 v = *(const float4*)(tab + (size_t)row * 128 + lane * 4);
    uint2 h, l;
    h.x = pack_hi(v.x, v.y); h.y = pack_hi(v.z, v.w);
    l.x = pack_lo(v.x, v.y); l.y = pack_lo(v.z, v.w);
    *(uint2*)(oh + (size_t)t * 128 + lane * 4) = h;
    *(uint2*)(ol + (size_t)t * 128 + lane * 4) = l;
}

// ---------------- attention logits + softmax ----------------
__global__ __launch_bounds__(256) void attn_kernel(
    const int* __restrict__ q_data,
    const float* __restrict__ q_table,
    const float* __restrict__ key_memory,
    float* __restrict__ w_out)
{
    __shared__ float ksm[32 * 129];
    int tid = threadIdx.x;
    for (int i = tid; i < 32 * 128; i += 256) {
        int m = i >> 7, k = i & 127;
        ksm[m * 129 + k] = key_memory[i];
    }
    __syncthreads();

    int warp = tid >> 5, lane = tid & 31;
    int t = blockIdx.x * 8 + warp;
    int row = q_data[t];

    float q0 = q_table[(size_t)row * 128 + lane];
    float q1 = q_table[(size_t)row * 128 + lane + 32];
    float q2 = q_table[(size_t)row * 128 + lane + 64];
    float q3 = q_table[(size_t)row * 128 + lane + 96];

    float lg = 0.f;
    #pragma unroll
    for (int k = 0; k < 128; ++k) {
        float qv;
        if (k < 32)       qv = __shfl_sync(0xffffffffu, q0, k & 31);
        else if (k < 64)  qv = __shfl_sync(0xffffffffu, q1, k & 31);
        else if (k < 96)  qv = __shfl_sync(0xffffffffu, q2, k & 31);
        else              qv = __shfl_sync(0xffffffffu, q3, k & 31);
        lg = fmaf(qv, ksm[lane * 129 + k], lg);
    }
    float mx = lg;
    #pragma unroll
    for (int off = 16; off > 0; off >>= 1)
        mx = fmaxf(mx, __shfl_xor_sync(0xffffffffu, mx, off));
    float e = expf(lg - mx);
    float sum = e;
    #pragma unroll
    for (int off = 16; off > 0; off >>= 1)
        sum += __shfl_xor_sync(0xffffffffu, sum, off);
    w_out[(size_t)t * 32 + lane] = e / sum;
}

// ---------------- bf16x3 tensor-core GEMM, KC=32, double-buffered, 2 CTAs/SM ----------------
struct GDesc {
    const __nv_bfloat16 *a0h, *a0l; int p0, o0;
    const __nv_bfloat16 *a1h, *a1l; int p1, o1;
    const __nv_bfloat16 *wh, *wl;   int ldk, wcol;
    const float* bias;
    int act;
    int omode;      // 0 fp32, 1 bf16 hi/lo
    float* outf; int ldo, ocol;
    __nv_bfloat16 *oh, *ol; int ldob, ocolb;
};

__device__ __forceinline__ void mma16816(float* c, const uint32_t* a, const uint32_t* b) {
    asm volatile(
        "mma.sync.aligned.m16n8k16.row.col.f32.bf16.bf16.f32 "
        "{%0,%1,%2,%3}, {%4,%5,%6,%7}, {%8,%9}, {%0,%1,%2,%3};"
        : "+f"(c[0]), "+f"(c[1]), "+f"(c[2]), "+f"(c[3])
        : "r"(a[0]), "r"(a[1]), "r"(a[2]), "r"(a[3]), "r"(b[0]), "r"(b[1]));
}
#define LDSM4(r, addr) \
    asm volatile("ldmatrix.sync.aligned.m8n8.x4.shared.b16 {%0,%1,%2,%3}, [%4];" \
        : "=r"((r)[0]), "=r"((r)[1]), "=r"((r)[2]), "=r"((r)[3]) : "r"(addr))

__device__ __forceinline__ void cpa16(uint32_t dst, const void* src) {
    asm volatile("cp.async.cg.shared.global [%0], [%1], 16;" :: "r"(dst), "l"(src));
}

// per-plane: 128 rows x 20 words (16 data + 4 pad) = 10240 B
constexpr int PLB = 10240;
constexpr int STB = 4 * PLB;       // stage bytes = 40960

__device__ __forceinline__ void prefetch_chunk(const GDesc& G, int tok0, int kbase,
                                               uint32_t stbase, int tid)
{
    const __nv_bfloat16 *Ah, *Al; int Ap, Ao;
    if (kbase < 128) { Ah = G.a0h; Al = G.a0l; Ap = G.p0; Ao = G.o0 + kbase; }
    else             { Ah = G.a1h; Al = G.a1l; Ap = G.p1; Ao = G.o1 + kbase - 128; }
    #pragma unroll
    for (int j = 0; j < 2; ++j) {
        int e = tid + j * 256;
        int r = e >> 2, q = e & 3;
        size_t src = (size_t)(tok0 + r) * Ap + Ao + q * 8;
        uint32_t dst = stbase + (uint32_t)(r * 80 + q * 16);
        cpa16(dst,       Ah + src);
        cpa16(dst + PLB, Al + src);
    }
    #pragma unroll
    for (int j = 0; j < 2; ++j) {
        int e = tid + j * 256;
        int n = e >> 2, q = e & 3;
        size_t src = (size_t)(G.wcol + n) * G.ldk + kbase + q * 8;
        uint32_t dst = stbase + 2u * PLB + (uint32_t)(n * 80 + q * 16);
        cpa16(dst,       G.wh + src);
        cpa16(dst + PLB, G.wl + src);
    }
}

__global__ __launch_bounds__(256, 2) void mma_gemm(int Ktot, GDesc G0, GDesc G1, GDesc G2)
{
    extern __shared__ __align__(16) uint32_t smw[];
    uint32_t sbase = (uint32_t)__cvta_generic_to_shared(smw);

    const GDesc G = (blockIdx.y == 0) ? G0 : ((blockIdx.y == 1) ? G1 : G2);

    int tid  = threadIdx.x;
    int wid  = tid >> 5, lane = tid & 31;
    int g    = lane >> 2, tq = lane & 3;
    int tok0 = blockIdx.x * 128;

    int wm = (wid & 1) * 64;
    int wn = (wid >> 1) * 32;

    // ldmatrix lane address offsets (bytes), row stride 80 B
    uint32_t arow = (uint32_t)((lane & 15) * 80 + (lane >> 4) * 16);
    int jb = lane >> 3;
    uint32_t brow = (uint32_t)((((jb >> 1) * 8) + (lane & 7)) * 80 + (jb & 1) * 16);

    float acc[4][4][4];
    #pragma unroll
    for (int i = 0; i < 4; ++i)
        #pragma unroll
        for (int j = 0; j < 4; ++j)
            #pragma unroll
            for (int u = 0; u < 4; ++u) acc[i][j][u] = 0.f;

    int nch = Ktot >> 5;   // KC = 32

    prefetch_chunk(G, tok0, 0, sbase, tid);
    asm volatile("cp.async.commit_group;");

    for (int c = 0; c < nch; ++c) {
        if (c + 1 < nch) {
            prefetch_chunk(G, tok0, (c + 1) << 5, sbase + (uint32_t)((c + 1) & 1) * STB, tid);
            asm volatile("cp.async.commit_group;");
            asm volatile("cp.async.wait_group 1;");
        } else {
            asm volatile("cp.async.wait_group 0;");
        }
        __syncthreads();

        uint32_t Ab = sbase + (uint32_t)(c & 1) * STB;
        uint32_t Bb = Ab + 2u * PLB;

        #pragma unroll
        for (int h = 0; h < 2; ++h) {
            uint32_t ah[4][4], al[4][4], bh[2][4], bl[2][4];
            #pragma unroll
            for (int mt = 0; mt < 4; ++mt) {
                uint32_t addr = Ab + (uint32_t)((wm + mt * 16) * 80) + arow + (uint32_t)(h * 32);
                LDSM4(ah[mt], addr);
                LDSM4(al[mt], addr + PLB);
            }
            #pragma unroll
            for (int ntp = 0; ntp < 2; ++ntp) {
                uint32_t addr = Bb + (uint32_t)((wn + ntp * 16) * 80) + brow + (uint32_t)(h * 32);
                LDSM4(bh[ntp], addr);
                LDSM4(bl[ntp], addr + PLB);
            }
            #pragma unroll
            for (int mt = 0; mt < 4; ++mt)
                #pragma unroll
                for (int nt = 0; nt < 4; ++nt)
                    mma16816(acc[mt][nt], ah[mt], &bh[nt >> 1][(nt & 1) * 2]);
            #pragma unroll
            for (int mt = 0; mt < 4; ++mt)
                #pragma unroll
                for (int nt = 0; nt < 4; ++nt)
                    mma16816(acc[mt][nt], ah[mt], &bl[nt >> 1][(nt & 1) * 2]);
            #pragma unroll
            for (int mt = 0; mt < 4; ++mt)
                #pragma unroll
                for (int nt = 0; nt < 4; ++nt)
                    mma16816(acc[mt][nt], al[mt], &bh[nt >> 1][(nt & 1) * 2]);
        }
        __syncthreads();
    }

    // epilogue
    #pragma unroll
    for (int nt = 0; nt < 4; ++nt) {
        int col = wn + nt * 8 + tq * 2;
        float2 bv = *(const float2*)(G.bias + col);
        #pragma unroll
        for (int mt = 0; mt < 4; ++mt) {
            int r0 = tok0 + wm + mt * 16 + g;
            float o00 = actf(acc[mt][nt][0] + bv.x, G.act);
            float o01 = actf(acc[mt][nt][1] + bv.y, G.act);
            float o10 = actf(acc[mt][nt][2] + bv.x, G.act);
            float o11 = actf(acc[mt][nt][3] + bv.y, G.act);
            if (G.omode == 0) {
                *(float2*)(G.outf + (size_t)r0 * G.ldo + G.ocol + col)     = make_float2(o00, o01);
                *(float2*)(G.outf + (size_t)(r0+8) * G.ldo + G.ocol + col) = make_float2(o10, o11);
            } else {
                *(uint32_t*)(G.oh + (size_t)r0 * G.ldob + G.ocolb + col)     = pack_hi(o00, o01);
                *(uint32_t*)(G.ol + (size_t)r0 * G.ldob + G.ocolb + col)     = pack_lo(o00, o01);
                *(uint32_t*)(G.oh + (size_t)(r0+8) * G.ldob + G.ocolb + col) = pack_hi(o10, o11);
                *(uint32_t*)(G.ol + (size_t)(r0+8) * G.ldob + G.ocolb + col) = pack_lo(o10, o11);
            }
        }
    }
}

// ---------------- DKVMN scan ----------------
__global__ __launch_bounds__(256) void scan_kernel(const float* __restrict__ ivm)
{
    int b   = blockIdx.x;
    int dh  = blockIdx.y * 64;
    int tid = threadIdx.x;
    int dl  = tid >> 2, mq = tid & 3;
    int d   = dh + dl;
    size_t tb = (size_t)b * S;

    float Mv[8];
    #pragma unroll
    for (int m = 0; m < 8; ++m)
        Mv[m] = ivm[(mq * 8 + m) * 128 + d];

    __shared__ float wsm[2][4][32];

    float e[4], a[4];
    if (tid < 128)
        wsm[0][tid >> 5][tid & 31] = g_w[(tb + (tid >> 5)) * 32 + (tid & 31)];
    #pragma unroll
    for (int s = 0; s < 4; ++s) {
        e[s] = g_erase[(tb + s) * 128 + d];
        a[s] = g_add  [(tb + s) * 128 + d];
    }
    __syncthreads();

    for (int gg = 0; gg < S / 4; ++gg) {
        int cur = gg & 1, nxt = cur ^ 1;
        int sbase = gg * 4;
        float en[4], an[4];
        if (gg + 1 < S / 4) {
            if (tid < 128)
                wsm[nxt][tid >> 5][tid & 31] = g_w[(tb + sbase + 4 + (tid >> 5)) * 32 + (tid & 31)];
            #pragma unroll
            for (int s = 0; s < 4; ++s) {
                en[s] = g_erase[(tb + sbase + 4 + s) * 128 + d];
                an[s] = g_add  [(tb + sbase + 4 + s) * 128 + d];
            }
        } else {
            #pragma unroll
            for (int s = 0; s < 4; ++s) { en[s] = 0.f; an[s] = 0.f; }
        }

        #pragma unroll
        for (int s = 0; s < 4; ++s) {
            float r = 0.f;
            #pragma unroll
            for (int m = 0; m < 8; ++m) {
                float wm = wsm[cur][s][mq * 8 + m];
                r = fmaf(wm, Mv[m], r);                        // read BEFORE write
                Mv[m] = fmaf(wm, fmaf(-Mv[m], e[s], a[s]), Mv[m]);
            }
            r += __shfl_xor_sync(0xffffffffu, r, 1);
            r += __shfl_xor_sync(0xffffffffu, r, 2);
            if (mq == 0) {
                __nv_bfloat16 h = __float2bfloat16(r);
                g_rd_h[(tb + sbase + s) * 128 + d] = h;
                g_rd_l[(tb + sbase + s) * 128 + d] = __float2bfloat16(r - __bfloat162float(h));
            }
        }
        __syncthreads();
        #pragma unroll
        for (int s = 0; s < 4; ++s) { e[s] = en[s]; a[s] = an[s]; }
    }
}

// ---------------- final heads ----------------
__global__ __launch_bounds__(128) void head_kernel(
    const float* __restrict__ W_ab2, const float* __restrict__ b_ab2,
    const float* __restrict__ W_df2, const float* __restrict__ b_df2,
    float* __restrict__ out)
{
    int warp = threadIdx.x >> 5, lane = threadIdx.x & 31;
    int t = blockIdx.x * 4 + warp;

    float pa = 0.f;
    #pragma unroll
    for (int j = 0; j < 8; ++j) {
        int k = lane + 32 * j;
        pa = fmaf(g_h[(size_t)t * 256 + k], W_ab2[k], pa);
    }
    float pd = 0.f;
    #pragma unroll
    for (int j = 0; j < 4; ++j) {
        int k = lane + 32 * j;
        pd = fmaf(g_d1[(size_t)t * 128 + k], W_df2[k], pd);
    }
    #pragma unroll
    for (int off = 16; off > 0; off >>= 1) {
        pa += __shfl_xor_sync(0xffffffffu, pa, off);
        pd += __shfl_xor_sync(0xffffffffu, pd, off);
    }
    if (lane == 0) {
        float ability    = pa + b_ab2[0];
        float difficulty = pd + b_df2[0];
        float z    = 3.0f * ability - difficulty;
        float pred = 1.f / (1.f + expf(-z));
        out[t]               = pred;
        out[(size_t)T + t]   = ability;
        out[(size_t)2*T + t] = difficulty;
        out[(size_t)3*T + t] = z;
    }
}

// ---------------- host launch ----------------
extern "C" void kernel_launch(void* const* d_in, const int* in_sizes, int n_in,
                              void* d_out, int out_size)
{
    const int*   q_data   = (const int*)  d_in[0];
    const int*   qa_data  = (const int*)  d_in[1];
    const float* q_table  = (const float*)d_in[2];
    const float* qa_table = (const float*)d_in[3];
    const float* key_mem  = (const float*)d_in[4];
    const float* init_vm  = (const float*)d_in[5];
    const float* W_erase  = (const float*)d_in[6];
    const float* b_erase  = (const float*)d_in[7];
    const float* W_add    = (const float*)d_in[8];
    const float* b_add    = (const float*)d_in[9];
    const float* W_sum    = (const float*)d_in[10];
    const float* b_sum    = (const float*)d_in[11];
    const float* W_ab1    = (const float*)d_in[12];
    const float* b_ab1    = (const float*)d_in[13];
    const float* W_ab2    = (const float*)d_in[14];
    const float* b_ab2    = (const float*)d_in[15];
    const float* W_df1    = (const float*)d_in[16];
    const float* b_df1    = (const float*)d_in[17];
    const float* W_df2    = (const float*)d_in[18];
    const float* b_df2    = (const float*)d_in[19];
    float* out = (float*)d_out;

    float *pw, *per, *pad, *ph, *pd1;
    __nv_bfloat16 *qeh, *qel, *qah, *qal, *rdh, *rdl, *smh, *sml;
    __nv_bfloat16 *Weh, *Wel, *Wah, *Wal, *Wdh, *Wdl, *Wsh, *Wsl, *Wbh, *Wbl;
    cudaGetSymbolAddress((void**)&pw,  g_w);
    cudaGetSymbolAddress((void**)&per, g_erase);
    cudaGetSymbolAddress((void**)&pad, g_add);
    cudaGetSymbolAddress((void**)&ph,  g_h);
    cudaGetSymbolAddress((void**)&pd1, g_d1);
    cudaGetSymbolAddress((void**)&qeh, g_qe_h); cudaGetSymbolAddress((void**)&qel, g_qe_l);
    cudaGetSymbolAddress((void**)&qah, g_qa_h); cudaGetSymbolAddress((void**)&qal, g_qa_l);
    cudaGetSymbolAddress((void**)&rdh, g_rd_h); cudaGetSymbolAddress((void**)&rdl, g_rd_l);
    cudaGetSymbolAddress((void**)&smh, g_sm_h); cudaGetSymbolAddress((void**)&sml, g_sm_l);
    cudaGetSymbolAddress((void**)&Weh, g_We_h); cudaGetSymbolAddress((void**)&Wel, g_We_l);
    cudaGetSymbolAddress((void**)&Wah, g_Wa_h); cudaGetSymbolAddress((void**)&Wal, g_Wa_l);
    cudaGetSymbolAddress((void**)&Wdh, g_Wd_h); cudaGetSymbolAddress((void**)&Wdl, g_Wd_l);
    cudaGetSymbolAddress((void**)&Wsh, g_Ws_h); cudaGetSymbolAddress((void**)&Wsl, g_Ws_l);
    cudaGetSymbolAddress((void**)&Wbh, g_Wb_h); cudaGetSymbolAddress((void**)&Wbl, g_Wb_l);

    constexpr int GSM = 2 * STB;   // 81920 B double-buffered -> 2 CTAs/SM
    cudaFuncSetAttribute(mma_gemm, cudaFuncAttributeMaxDynamicSharedMemorySize, GSM);

    const int MT = T / 128;

    prep_weight_all<<<704, 256>>>(W_erase, W_add, W_df1, W_sum, W_ab1);
    prep_gather<<<dim3(T / 8, 2), 256>>>(q_data, q_table, qa_data, qa_table);
    attn_kernel<<<T / 8, 256>>>(q_data, q_table, key_mem, pw);

    // erase / add / df1 fused (K=128)
    GDesc Ge = { qah, qal, 128, 0,  nullptr, nullptr, 0, 0,
                 Weh, Wel, 128, 0,  b_erase, 1, 0, per, 128, 0, nullptr, nullptr, 0, 0 };
    GDesc Ga = { qah, qal, 128, 0,  nullptr, nullptr, 0, 0,
                 Wah, Wal, 128, 0,  b_add,   2, 0, pad, 128, 0, nullptr, nullptr, 0, 0 };
    GDesc Gd = { qeh, qel, 128, 0,  nullptr, nullptr, 0, 0,
                 Wdh, Wdl, 128, 0,  b_df1,   2, 0, pd1, 128, 0, nullptr, nullptr, 0, 0 };
    mma_gemm<<<dim3(MT, 3), 256, GSM>>>(128, Ge, Ga, Gd);

    scan_kernel<<<dim3(B, 2), 256>>>(init_vm);

    // summary = tanh([reads | qe] @ W_sum + b), K=256, out bf16 hi/lo
    GDesc Gs0 = { rdh, rdl, 128, 0,  qeh, qel, 128, 0,
                  Wsh, Wsl, 256, 0,    b_sum,       2, 1, nullptr, 0, 0, smh, sml, 256, 0 };
    GDesc Gs1 = { rdh, rdl, 128, 0,  qeh, qel, 128, 0,
                  Wsh, Wsl, 256, 128,  b_sum + 128, 2, 1, nullptr, 0, 0, smh, sml, 256, 128 };
    mma_gemm<<<dim3(MT, 2), 256, GSM>>>(256, Gs0, Gs1, Gs1);

    // ability hidden = tanh(summary @ W_ab1 + b), K=256
    GDesc Gb0 = { smh, sml, 256, 0,  smh, sml, 256, 128,
                  Wbh, Wbl, 256, 0,    b_ab1,       2, 0, ph, 256, 0,   nullptr, nullptr, 0, 0 };
    GDesc Gb1 = { smh, sml, 256, 0,  smh, sml, 256, 128,
                  Wbh, Wbl, 256, 128,  b_ab1 + 128, 2, 0, ph, 256, 128, nullptr, nullptr, 0, 0 };
    mma_gemm<<<dim3(MT, 2), 256, GSM>>>(256, Gb0, Gb1, Gb1);

    head_kernel<<<T / 4, 128>>>(W_ab2, b_ab2, W_df2, b_df2, out);
}

// round 7
// speedup vs baseline: 2.0879x; 1.0828x over previous
#include <cuda_runtime.h>
#include <cuda_bf16.h>
#include <math.h>
#include <stdint.h>

constexpr int B   = 256;
constexpr int S   = 512;
constexpr int T   = B * S;       // 131072 tokens
constexpr int MEM = 32;
constexpr int DK  = 128;
constexpr int DV  = 128;
constexpr int DS  = 256;

// ---------------- scratch ----------------
__device__ float g_w    [(size_t)T * MEM];
__device__ float g_erase[(size_t)T * DV];
__device__ float g_add  [(size_t)T * DV];
__device__ float g_h    [(size_t)T * DS];
__device__ float g_d1   [(size_t)T * DK];

__device__ __nv_bfloat16 g_qe_h[(size_t)T * 128], g_qe_l[(size_t)T * 128];
__device__ __nv_bfloat16 g_qa_h[(size_t)T * 128], g_qa_l[(size_t)T * 128];
__device__ __nv_bfloat16 g_rd_h[(size_t)T * 128], g_rd_l[(size_t)T * 128];
__device__ __nv_bfloat16 g_sm_h[(size_t)T * 256], g_sm_l[(size_t)T * 256];

__device__ __nv_bfloat16 g_We_h[128*128], g_We_l[128*128];
__device__ __nv_bfloat16 g_Wa_h[128*128], g_Wa_l[128*128];
__device__ __nv_bfloat16 g_Wd_h[128*128], g_Wd_l[128*128];
__device__ __nv_bfloat16 g_Ws_h[256*256], g_Ws_l[256*256];
__device__ __nv_bfloat16 g_Wb_h[256*256], g_Wb_l[256*256];

__device__ __forceinline__ float actf(float x, int a) {
    if (a == 1) return 1.f / (1.f + expf(-x));
    if (a == 2) return tanhf(x);
    return x;
}
__device__ __forceinline__ uint32_t pack_hi(float x, float y) {
    __nv_bfloat16 hx = __float2bfloat16(x);
    __nv_bfloat16 hy = __float2bfloat16(y);
    return ((uint32_t)__bfloat16_as_ushort(hy) << 16) | __bfloat16_as_ushort(hx);
}
__device__ __forceinline__ uint32_t pack_lo(float x, float y) {
    __nv_bfloat16 hx = __float2bfloat16(x);
    __nv_bfloat16 hy = __float2bfloat16(y);
    __nv_bfloat16 lx = __float2bfloat16(x - __bfloat162float(hx));
    __nv_bfloat16 ly = __float2bfloat16(y - __bfloat162float(hy));
    return ((uint32_t)__bfloat16_as_ushort(ly) << 16) | __bfloat16_as_ushort(lx);
}

// ---------------- prep: all 5 weights, one launch ----------------
__global__ __launch_bounds__(256) void prep_weight_all(
    const float* __restrict__ W0, const float* __restrict__ W1,
    const float* __restrict__ W2, const float* __restrict__ W3,
    const float* __restrict__ W4)
{
    int bid = blockIdx.x;
    const float* W; __nv_bfloat16 *th, *tl; int K, N, base;
    if (bid < 64)       { W = W0; th = g_We_h; tl = g_We_l; K = 128; N = 128; base = 0; }
    else if (bid < 128) { W = W1; th = g_Wa_h; tl = g_Wa_l; K = 128; N = 128; base = 64; }
    else if (bid < 192) { W = W2; th = g_Wd_h; tl = g_Wd_l; K = 128; N = 128; base = 128; }
    else if (bid < 448) { W = W3; th = g_Ws_h; tl = g_Ws_l; K = 256; N = 256; base = 192; }
    else                { W = W4; th = g_Wb_h; tl = g_Wb_l; K = 256; N = 256; base = 448; }
    int e = (bid - base) * 256 + threadIdx.x;
    int k = e / N, n = e - k * N;
    float v = W[e];
    __nv_bfloat16 h = __float2bfloat16(v);
    th[(size_t)n * K + k] = h;
    tl[(size_t)n * K + k] = __float2bfloat16(v - __bfloat162float(h));
}

// ---------------- prep: gather + fp32 -> bf16 hi/lo ----------------
__global__ __launch_bounds__(256) void prep_gather(
    const int* __restrict__ q_data, const float* __restrict__ q_table,
    const int* __restrict__ qa_data, const float* __restrict__ qa_table)
{
    int t    = blockIdx.x * 8 + (threadIdx.x >> 5);
    int lane = threadIdx.x & 31;
    const int*   idx;
    const float* tab;
    __nv_bfloat16 *oh, *ol;
    if (blockIdx.y == 0) { idx = q_data;  tab = q_table;  oh = g_qe_h; ol = g_qe_l; }
    else                 { idx = qa_data; tab = qa_table; oh = g_qa_h; ol = g_qa_l; }
    int row = idx[t];
    float4 v = *(const float4*)(tab + (size_t)row * 128 + lane * 4);
    uint2 h, l;
    h.x = pack_hi(v.x, v.y); h.y = pack_hi(v.z, v.w);
    l.x = pack_lo(v.x, v.y); l.y = pack_lo(v.z, v.w);
    *(uint2*)(oh + (size_t)t * 128 + lane * 4) = h;
    *(uint2*)(ol + (size_t)t * 128 + lane * 4) = l;
}

// ---------------- attention logits + softmax ----------------
__global__ __launch_bounds__(256) void attn_kernel(
    const int* __restrict__ q_data,
    const float* __restrict__ q_table,
    const float* __restrict__ key_memory,
    float* __restrict__ w_out)
{
    __shared__ float ksm[32 * 129];
    int tid = threadIdx.x;
    for (int i = tid; i < 32 * 128; i += 256) {
        int m = i >> 7, k = i & 127;
        ksm[m * 129 + k] = key_memory[i];
    }
    __syncthreads();

    int warp = tid >> 5, lane = tid & 31;
    int t = blockIdx.x * 8 + warp;
    int row = q_data[t];

    float q0 = q_table[(size_t)row * 128 + lane];
    float q1 = q_table[(size_t)row * 128 + lane + 32];
    float q2 = q_table[(size_t)row * 128 + lane + 64];
    float q3 = q_table[(size_t)row * 128 + lane + 96];

    float lg = 0.f;
    #pragma unroll
    for (int k = 0; k < 128; ++k) {
        float qv;
        if (k < 32)       qv = __shfl_sync(0xffffffffu, q0, k & 31);
        else if (k < 64)  qv = __shfl_sync(0xffffffffu, q1, k & 31);
        else if (k < 96)  qv = __shfl_sync(0xffffffffu, q2, k & 31);
        else              qv = __shfl_sync(0xffffffffu, q3, k & 31);
        lg = fmaf(qv, ksm[lane * 129 + k], lg);
    }
    float mx = lg;
    #pragma unroll
    for (int off = 16; off > 0; off >>= 1)
        mx = fmaxf(mx, __shfl_xor_sync(0xffffffffu, mx, off));
    float e = expf(lg - mx);
    float sum = e;
    #pragma unroll
    for (int off = 16; off > 0; off >>= 1)
        sum += __shfl_xor_sync(0xffffffffu, sum, off);
    w_out[(size_t)t * 32 + lane] = e / sum;
}

// ---------------- bf16x3 GEMM: B-resident, 3-stage A ring, 1 sync/chunk ----------------
struct GDesc {
    const __nv_bfloat16 *a0h, *a0l; int p0, o0;
    const __nv_bfloat16 *a1h, *a1l; int p1, o1;
    const __nv_bfloat16 *wh, *wl;   int ldk, wcol;
    const float* bias;
    int act;
    int omode;      // 0 fp32, 1 bf16 hi/lo
    float* outf; int ldo, ocol;
    __nv_bfloat16 *oh, *ol; int ldob, ocolb;
};

__device__ __forceinline__ void mma16816(float* c, const uint32_t* a, const uint32_t* b) {
    asm volatile(
        "mma.sync.aligned.m16n8k16.row.col.f32.bf16.bf16.f32 "
        "{%0,%1,%2,%3}, {%4,%5,%6,%7}, {%8,%9}, {%0,%1,%2,%3};"
        : "+f"(c[0]), "+f"(c[1]), "+f"(c[2]), "+f"(c[3])
        : "r"(a[0]), "r"(a[1]), "r"(a[2]), "r"(a[3]), "r"(b[0]), "r"(b[1]));
}
#define LDSM4(r, addr) \
    asm volatile("ldmatrix.sync.aligned.m8n8.x4.shared.b16 {%0,%1,%2,%3}, [%4];" \
        : "=r"((r)[0]), "=r"((r)[1]), "=r"((r)[2]), "=r"((r)[3]) : "r"(addr))

__device__ __forceinline__ void cpa16(uint32_t dst, const void* src) {
    asm volatile("cp.async.cg.shared.global [%0], [%1], 16;" :: "r"(dst), "l"(src));
}

constexpr int APL  = 8192;           // A plane bytes per stage (128 rows x 64 B)
constexpr int AST  = 2 * APL;        // A stage (hi+lo) = 16384
constexpr int BPL  = 32768;          // B plane bytes (128 rows x 256 B)
constexpr int AOFF = 2 * BPL;        // 65536
constexpr int GSM  = AOFF + 3 * AST; // 114688 -> 2 CTAs/SM

// A chunk: 128 rows x 32 halves. granule swizzle q' = q ^ ((r>>1)&3)
__device__ __forceinline__ void prefetch_A(const GDesc& G, int tok0, int c,
                                           uint32_t stage_base, int tid)
{
    int kbase = c << 5;
    const __nv_bfloat16 *Ah, *Al; int Ap, Ao;
    if (kbase < 128) { Ah = G.a0h; Al = G.a0l; Ap = G.p0; Ao = G.o0 + kbase; }
    else             { Ah = G.a1h; Al = G.a1l; Ap = G.p1; Ao = G.o1 + kbase - 128; }
    #pragma unroll
    for (int j = 0; j < 2; ++j) {
        int e = tid + j * 256;
        int r = e >> 2, q = e & 3;
        int qs = q ^ ((r >> 1) & 3);
        size_t src = (size_t)(tok0 + r) * Ap + Ao + q * 8;
        uint32_t dst = stage_base + (uint32_t)(r * 64 + qs * 16);
        cpa16(dst,       Ah + src);
        cpa16(dst + APL, Al + src);
    }
}

// B half: 128 n-rows x 128 k-halves. granule swizzle q' = q ^ (n&7)
__device__ __forceinline__ void load_B(const GDesc& G, int khalf, uint32_t sbase, int tid)
{
    #pragma unroll
    for (int j = 0; j < 8; ++j) {
        int e = tid + j * 256;
        int n = e >> 4, q = e & 15;
        int qs = q ^ (n & 7);
        size_t src = (size_t)(G.wcol + n) * G.ldk + khalf + q * 8;
        uint32_t dst = sbase + (uint32_t)(n * 256 + qs * 16);
        cpa16(dst,       G.wh + src);
        cpa16(dst + BPL, G.wl + src);
    }
}

__global__ __launch_bounds__(256, 2) void mma_gemm(int Ktot, GDesc G0, GDesc G1, GDesc G2)
{
    extern __shared__ __align__(16) uint32_t smw[];
    uint32_t sbase = (uint32_t)__cvta_generic_to_shared(smw);

    const GDesc G = (blockIdx.y == 0) ? G0 : ((blockIdx.y == 1) ? G1 : G2);

    int tid  = threadIdx.x;
    int wid  = tid >> 5, lane = tid & 31;
    int g    = lane >> 2, tq = lane & 3;
    int tok0 = blockIdx.x * 128;

    int wm = (wid & 1) * 64;
    int wn = (wid >> 1) * 32;

    // hoisted fragment address components
    int lane_r = lane & 15;
    int a_qb   = lane >> 4;                 // 0/1
    int jb     = lane >> 3;
    uint32_t a_row[4]; int a_sw[4];
    #pragma unroll
    for (int mt = 0; mt < 4; ++mt) {
        int r = wm + mt * 16 + lane_r;
        a_row[mt] = (uint32_t)(r * 64);
        a_sw[mt]  = (r >> 1) & 3;
    }
    uint32_t b_row[2]; int b_sw[2];
    #pragma unroll
    for (int ntp = 0; ntp < 2; ++ntp) {
        int n = wn + ntp * 16 + ((jb >> 1) * 8) + (lane & 7);
        b_row[ntp] = (uint32_t)(n * 256);
        b_sw[ntp]  = n & 7;
    }
    int b_qb = jb & 1;

    float acc[4][4][4];
    #pragma unroll
    for (int i = 0; i < 4; ++i)
        #pragma unroll
        for (int j = 0; j < 4; ++j)
            #pragma unroll
            for (int u = 0; u < 4; ++u) acc[i][j][u] = 0.f;

    int nch = Ktot >> 5;   // KC = 32

    // prologue: B half0 + A0 (group0), A1 (group1)
    load_B(G, 0, sbase, tid);
    prefetch_A(G, tok0, 0, sbase + AOFF, tid);
    asm volatile("cp.async.commit_group;");
    if (nch > 1) prefetch_A(G, tok0, 1, sbase + AOFF + AST, tid);
    asm volatile("cp.async.commit_group;");

    for (int c = 0; c < nch; ++c) {
        asm volatile("cp.async.wait_group 1;");
        __syncthreads();
        if (c == 4) {                         // only reached when nch == 8: B swap
            load_B(G, 128, sbase, tid);
            if (c + 2 < nch) {
                int s = (c + 2) % 3;
                prefetch_A(G, tok0, c + 2, sbase + AOFF + (uint32_t)s * AST, tid);
            }
            asm volatile("cp.async.commit_group;");
            asm volatile("cp.async.wait_group 0;");
            __syncthreads();
        } else {
            if (c + 2 < nch) {
                int s = (c + 2) % 3;
                prefetch_A(G, tok0, c + 2, sbase + AOFF + (uint32_t)s * AST, tid);
            }
            asm volatile("cp.async.commit_group;");
        }

        uint32_t Ab = sbase + AOFF + (uint32_t)(c % 3) * AST;
        int bq_c = (c & 3) * 4 + b_qb;

        #pragma unroll
        for (int h = 0; h < 2; ++h) {
            uint32_t ah[4][4], al[4][4], bh[2][4], bl[2][4];
            int aq = h * 2 + a_qb;
            #pragma unroll
            for (int mt = 0; mt < 4; ++mt) {
                uint32_t addr = Ab + a_row[mt] + (uint32_t)((aq ^ a_sw[mt]) << 4);
                LDSM4(ah[mt], addr);
                LDSM4(al[mt], addr + APL);
            }
            int bq = bq_c + h * 2;
            #pragma unroll
            for (int ntp = 0; ntp < 2; ++ntp) {
                uint32_t addr = sbase + b_row[ntp] + (uint32_t)((bq ^ b_sw[ntp]) << 4);
                LDSM4(bh[ntp], addr);
                LDSM4(bl[ntp], addr + BPL);
            }
            #pragma unroll
            for (int mt = 0; mt < 4; ++mt)
                #pragma unroll
                for (int nt = 0; nt < 4; ++nt)
                    mma16816(acc[mt][nt], ah[mt], &bh[nt >> 1][(nt & 1) * 2]);
            #pragma unroll
            for (int mt = 0; mt < 4; ++mt)
                #pragma unroll
                for (int nt = 0; nt < 4; ++nt)
                    mma16816(acc[mt][nt], ah[mt], &bl[nt >> 1][(nt & 1) * 2]);
            #pragma unroll
            for (int mt = 0; mt < 4; ++mt)
                #pragma unroll
                for (int nt = 0; nt < 4; ++nt)
                    mma16816(acc[mt][nt], al[mt], &bh[nt >> 1][(nt & 1) * 2]);
        }
    }

    // epilogue
    #pragma unroll
    for (int nt = 0; nt < 4; ++nt) {
        int col = wn + nt * 8 + tq * 2;
        float2 bv = *(const float2*)(G.bias + col);
        #pragma unroll
        for (int mt = 0; mt < 4; ++mt) {
            int r0 = tok0 + wm + mt * 16 + g;
            float o00 = actf(acc[mt][nt][0] + bv.x, G.act);
            float o01 = actf(acc[mt][nt][1] + bv.y, G.act);
            float o10 = actf(acc[mt][nt][2] + bv.x, G.act);
            float o11 = actf(acc[mt][nt][3] + bv.y, G.act);
            if (G.omode == 0) {
                *(float2*)(G.outf + (size_t)r0 * G.ldo + G.ocol + col)     = make_float2(o00, o01);
                *(float2*)(G.outf + (size_t)(r0+8) * G.ldo + G.ocol + col) = make_float2(o10, o11);
            } else {
                *(uint32_t*)(G.oh + (size_t)r0 * G.ldob + G.ocolb + col)     = pack_hi(o00, o01);
                *(uint32_t*)(G.ol + (size_t)r0 * G.ldob + G.ocolb + col)     = pack_lo(o00, o01);
                *(uint32_t*)(G.oh + (size_t)(r0+8) * G.ldob + G.ocolb + col) = pack_hi(o10, o11);
                *(uint32_t*)(G.ol + (size_t)(r0+8) * G.ldob + G.ocolb + col) = pack_lo(o10, o11);
            }
        }
    }
}

// ---------------- DKVMN scan ----------------
__global__ __launch_bounds__(256) void scan_kernel(const float* __restrict__ ivm)
{
    int b   = blockIdx.x;
    int dh  = blockIdx.y * 64;
    int tid = threadIdx.x;
    int dl  = tid >> 2, mq = tid & 3;
    int d   = dh + dl;
    size_t tb = (size_t)b * S;

    float Mv[8];
    #pragma unroll
    for (int m = 0; m < 8; ++m)
        Mv[m] = ivm[(mq * 8 + m) * 128 + d];

    __shared__ float wsm[2][4][32];

    float e[4], a[4];
    if (tid < 128)
        wsm[0][tid >> 5][tid & 31] = g_w[(tb + (tid >> 5)) * 32 + (tid & 31)];
    #pragma unroll
    for (int s = 0; s < 4; ++s) {
        e[s] = g_erase[(tb + s) * 128 + d];
        a[s] = g_add  [(tb + s) * 128 + d];
    }
    __syncthreads();

    for (int gg = 0; gg < S / 4; ++gg) {
        int cur = gg & 1, nxt = cur ^ 1;
        int sbase = gg * 4;
        float en[4], an[4];
        if (gg + 1 < S / 4) {
            if (tid < 128)
                wsm[nxt][tid >> 5][tid & 31] = g_w[(tb + sbase + 4 + (tid >> 5)) * 32 + (tid & 31)];
            #pragma unroll
            for (int s = 0; s < 4; ++s) {
                en[s] = g_erase[(tb + sbase + 4 + s) * 128 + d];
                an[s] = g_add  [(tb + sbase + 4 + s) * 128 + d];
            }
        } else {
            #pragma unroll
            for (int s = 0; s < 4; ++s) { en[s] = 0.f; an[s] = 0.f; }
        }

        #pragma unroll
        for (int s = 0; s < 4; ++s) {
            float r = 0.f;
            #pragma unroll
            for (int m = 0; m < 8; ++m) {
                float wm = wsm[cur][s][mq * 8 + m];
                r = fmaf(wm, Mv[m], r);                        // read BEFORE write
                Mv[m] = fmaf(wm, fmaf(-Mv[m], e[s], a[s]), Mv[m]);
            }
            r += __shfl_xor_sync(0xffffffffu, r, 1);
            r += __shfl_xor_sync(0xffffffffu, r, 2);
            if (mq == 0) {
                __nv_bfloat16 h = __float2bfloat16(r);
                g_rd_h[(tb + sbase + s) * 128 + d] = h;
                g_rd_l[(tb + sbase + s) * 128 + d] = __float2bfloat16(r - __bfloat162float(h));
            }
        }
        __syncthreads();
        #pragma unroll
        for (int s = 0; s < 4; ++s) { e[s] = en[s]; a[s] = an[s]; }
    }
}

// ---------------- final heads ----------------
__global__ __launch_bounds__(128) void head_kernel(
    const float* __restrict__ W_ab2, const float* __restrict__ b_ab2,
    const float* __restrict__ W_df2, const float* __restrict__ b_df2,
    float* __restrict__ out)
{
    int warp = threadIdx.x >> 5, lane = threadIdx.x & 31;
    int t = blockIdx.x * 4 + warp;

    float pa = 0.f;
    #pragma unroll
    for (int j = 0; j < 8; ++j) {
        int k = lane + 32 * j;
        pa = fmaf(g_h[(size_t)t * 256 + k], W_ab2[k], pa);
    }
    float pd = 0.f;
    #pragma unroll
    for (int j = 0; j < 4; ++j) {
        int k = lane + 32 * j;
        pd = fmaf(g_d1[(size_t)t * 128 + k], W_df2[k], pd);
    }
    #pragma unroll
    for (int off = 16; off > 0; off >>= 1) {
        pa += __shfl_xor_sync(0xffffffffu, pa, off);
        pd += __shfl_xor_sync(0xffffffffu, pd, off);
    }
    if (lane == 0) {
        float ability    = pa + b_ab2[0];
        float difficulty = pd + b_df2[0];
        float z    = 3.0f * ability - difficulty;
        float pred = 1.f / (1.f + expf(-z));
        out[t]               = pred;
        out[(size_t)T + t]   = ability;
        out[(size_t)2*T + t] = difficulty;
        out[(size_t)3*T + t] = z;
    }
}

// ---------------- host launch ----------------
extern "C" void kernel_launch(void* const* d_in, const int* in_sizes, int n_in,
                              void* d_out, int out_size)
{
    const int*   q_data   = (const int*)  d_in[0];
    const int*   qa_data  = (const int*)  d_in[1];
    const float* q_table  = (const float*)d_in[2];
    const float* qa_table = (const float*)d_in[3];
    const float* key_mem  = (const float*)d_in[4];
    const float* init_vm  = (const float*)d_in[5];
    const float* W_erase  = (const float*)d_in[6];
    const float* b_erase  = (const float*)d_in[7];
    const float* W_add    = (const float*)d_in[8];
    const float* b_add    = (const float*)d_in[9];
    const float* W_sum    = (const float*)d_in[10];
    const float* b_sum    = (const float*)d_in[11];
    const float* W_ab1    = (const float*)d_in[12];
    const float* b_ab1    = (const float*)d_in[13];
    const float* W_ab2    = (const float*)d_in[14];
    const float* b_ab2    = (const float*)d_in[15];
    const float* W_df1    = (const float*)d_in[16];
    const float* b_df1    = (const float*)d_in[17];
    const float* W_df2    = (const float*)d_in[18];
    const float* b_df2    = (const float*)d_in[19];
    float* out = (float*)d_out;

    float *pw, *per, *pad, *ph, *pd1;
    __nv_bfloat16 *qeh, *qel, *qah, *qal, *rdh, *rdl, *smh, *sml;
    __nv_bfloat16 *Weh, *Wel, *Wah, *Wal, *Wdh, *Wdl, *Wsh, *Wsl, *Wbh, *Wbl;
    cudaGetSymbolAddress((void**)&pw,  g_w);
    cudaGetSymbolAddress((void**)&per, g_erase);
    cudaGetSymbolAddress((void**)&pad, g_add);
    cudaGetSymbolAddress((void**)&ph,  g_h);
    cudaGetSymbolAddress((void**)&pd1, g_d1);
    cudaGetSymbolAddress((void**)&qeh, g_qe_h); cudaGetSymbolAddress((void**)&qel, g_qe_l);
    cudaGetSymbolAddress((void**)&qah, g_qa_h); cudaGetSymbolAddress((void**)&qal, g_qa_l);
    cudaGetSymbolAddress((void**)&rdh, g_rd_h); cudaGetSymbolAddress((void**)&rdl, g_rd_l);
    cudaGetSymbolAddress((void**)&smh, g_sm_h); cudaGetSymbolAddress((void**)&sml, g_sm_l);
    cudaGetSymbolAddress((void**)&Weh, g_We_h); cudaGetSymbolAddress((void**)&Wel, g_We_l);
    cudaGetSymbolAddress((void**)&Wah, g_Wa_h); cudaGetSymbolAddress((void**)&Wal, g_Wa_l);
    cudaGetSymbolAddress((void**)&Wdh, g_Wd_h); cudaGetSymbolAddress((void**)&Wdl, g_Wd_l);
    cudaGetSymbolAddress((void**)&Wsh, g_Ws_h); cudaGetSymbolAddress((void**)&Wsl, g_Ws_l);
    cudaGetSymbolAddress((void**)&Wbh, g_Wb_h); cudaGetSymbolAddress((void**)&Wbl, g_Wb_l);

    cudaFuncSetAttribute(mma_gemm, cudaFuncAttributeMaxDynamicSharedMemorySize, GSM);

    const int MT = T / 128;

    prep_weight_all<<<704, 256>>>(W_erase, W_add, W_df1, W_sum, W_ab1);
    prep_gather<<<dim3(T / 8, 2), 256>>>(q_data, q_table, qa_data, qa_table);
    attn_kernel<<<T / 8, 256>>>(q_data, q_table, key_mem, pw);

    // erase / add / df1 fused (K=128)
    GDesc Ge = { qah, qal, 128, 0,  nullptr, nullptr, 0, 0,
                 Weh, Wel, 128, 0,  b_erase, 1, 0, per, 128, 0, nullptr, nullptr, 0, 0 };
    GDesc Ga = { qah, qal, 128, 0,  nullptr, nullptr, 0, 0,
                 Wah, Wal, 128, 0,  b_add,   2, 0, pad, 128, 0, nullptr, nullptr, 0, 0 };
    GDesc Gd = { qeh, qel, 128, 0,  nullptr, nullptr, 0, 0,
                 Wdh, Wdl, 128, 0,  b_df1,   2, 0, pd1, 128, 0, nullptr, nullptr, 0, 0 };
    mma_gemm<<<dim3(MT, 3), 256, GSM>>>(128, Ge, Ga, Gd);

    scan_kernel<<<dim3(B, 2), 256>>>(init_vm);

    // summary = tanh([reads | qe] @ W_sum + b), K=256, out bf16 hi/lo
    GDesc Gs0 = { rdh, rdl, 128, 0,  qeh, qel, 128, 0,
                  Wsh, Wsl, 256, 0,    b_sum,       2, 1, nullptr, 0, 0, smh, sml, 256, 0 };
    GDesc Gs1 = { rdh, rdl, 128, 0,  qeh, qel, 128, 0,
                  Wsh, Wsl, 256, 128,  b_sum + 128, 2, 1, nullptr, 0, 0, smh, sml, 256, 128 };
    mma_gemm<<<dim3(MT, 2), 256, GSM>>>(256, Gs0, Gs1, Gs1);

    // ability hidden = tanh(summary @ W_ab1 + b), K=256
    GDesc Gb0 = { smh, sml, 256, 0,  smh, sml, 256, 128,
                  Wbh, Wbl, 256, 0,    b_ab1,       2, 0, ph, 256, 0,   nullptr, nullptr, 0, 0 };
    GDesc Gb1 = { smh, sml, 256, 0,  smh, sml, 256, 128,
                  Wbh, Wbl, 256, 128,  b_ab1 + 128, 2, 0, ph, 256, 128, nullptr, nullptr, 0, 0 };
    mma_gemm<<<dim3(MT, 2), 256, GSM>>>(256, Gb0, Gb1, Gb1);

    head_kernel<<<T / 4, 128>>>(W_ab2, b_ab2, W_df2, b_df2, out);
}

// round 8
// speedup vs baseline: 2.1310x; 1.0207x over previous
#include <cuda_runtime.h>
#include <cuda_bf16.h>
#include <math.h>
#include <stdint.h>

constexpr int B   = 256;
constexpr int S   = 512;
constexpr int T   = B * S;       // 131072 tokens
constexpr int MEM = 32;
constexpr int DK  = 128;
constexpr int DV  = 128;
constexpr int DS  = 256;

// ---------------- scratch ----------------
__device__ float g_w    [(size_t)T * MEM];
__device__ float g_erase[(size_t)T * DV];
__device__ float g_add  [(size_t)T * DV];
__device__ float g_pa   [(size_t)2 * T];    // ability partial dots (2 N-halves)
__device__ float g_pd   [(size_t)T];        // difficulty dot

__device__ __nv_bfloat16 g_qe_h[(size_t)T * 128], g_qe_l[(size_t)T * 128];
__device__ __nv_bfloat16 g_qa_h[(size_t)T * 128], g_qa_l[(size_t)T * 128];
__device__ __nv_bfloat16 g_rd_h[(size_t)T * 128], g_rd_l[(size_t)T * 128];
__device__ __nv_bfloat16 g_sm_h[(size_t)T * 256], g_sm_l[(size_t)T * 256];

__device__ __nv_bfloat16 g_We_h[128*128], g_We_l[128*128];
__device__ __nv_bfloat16 g_Wa_h[128*128], g_Wa_l[128*128];
__device__ __nv_bfloat16 g_Wd_h[128*128], g_Wd_l[128*128];
__device__ __nv_bfloat16 g_Ws_h[256*256], g_Ws_l[256*256];
__device__ __nv_bfloat16 g_Wb_h[256*256], g_Wb_l[256*256];

__device__ __forceinline__ float actf(float x, int a) {
    if (a == 1) return 1.f / (1.f + expf(-x));
    if (a == 2) return tanhf(x);
    return x;
}
__device__ __forceinline__ uint32_t pack_hi(float x, float y) {
    __nv_bfloat16 hx = __float2bfloat16(x);
    __nv_bfloat16 hy = __float2bfloat16(y);
    return ((uint32_t)__bfloat16_as_ushort(hy) << 16) | __bfloat16_as_ushort(hx);
}
__device__ __forceinline__ uint32_t pack_lo(float x, float y) {
    __nv_bfloat16 hx = __float2bfloat16(x);
    __nv_bfloat16 hy = __float2bfloat16(y);
    __nv_bfloat16 lx = __float2bfloat16(x - __bfloat162float(hx));
    __nv_bfloat16 ly = __float2bfloat16(y - __bfloat162float(hy));
    return ((uint32_t)__bfloat16_as_ushort(ly) << 16) | __bfloat16_as_ushort(lx);
}

// ---------------- prep: all 5 weights, one launch ----------------
__global__ __launch_bounds__(256) void prep_weight_all(
    const float* __restrict__ W0, const float* __restrict__ W1,
    const float* __restrict__ W2, const float* __restrict__ W3,
    const float* __restrict__ W4)
{
    int bid = blockIdx.x;
    const float* W; __nv_bfloat16 *th, *tl; int K, N, base;
    if (bid < 64)       { W = W0; th = g_We_h; tl = g_We_l; K = 128; N = 128; base = 0; }
    else if (bid < 128) { W = W1; th = g_Wa_h; tl = g_Wa_l; K = 128; N = 128; base = 64; }
    else if (bid < 192) { W = W2; th = g_Wd_h; tl = g_Wd_l; K = 128; N = 128; base = 128; }
    else if (bid < 448) { W = W3; th = g_Ws_h; tl = g_Ws_l; K = 256; N = 256; base = 192; }
    else                { W = W4; th = g_Wb_h; tl = g_Wb_l; K = 256; N = 256; base = 448; }
    int e = (bid - base) * 256 + threadIdx.x;
    int k = e / N, n = e - k * N;
    float v = W[e];
    __nv_bfloat16 h = __float2bfloat16(v);
    th[(size_t)n * K + k] = h;
    tl[(size_t)n * K + k] = __float2bfloat16(v - __bfloat162float(h));
}

// ---------------- prep: qa gather + fp32 -> bf16 hi/lo ----------------
__global__ __launch_bounds__(256) void prep_gather_qa(
    const int* __restrict__ qa_data, const float* __restrict__ qa_table)
{
    int t    = blockIdx.x * 8 + (threadIdx.x >> 5);
    int lane = threadIdx.x & 31;
    int row = qa_data[t];
    float4 v = *(const float4*)(qa_table + (size_t)row * 128 + lane * 4);
    uint2 h, l;
    h.x = pack_hi(v.x, v.y); h.y = pack_hi(v.z, v.w);
    l.x = pack_lo(v.x, v.y); l.y = pack_lo(v.z, v.w);
    *(uint2*)(g_qa_h + (size_t)t * 128 + lane * 4) = h;
    *(uint2*)(g_qa_l + (size_t)t * 128 + lane * 4) = l;
}

// ---------------- attention softmax + qe bf16 conversion ----------------
__global__ __launch_bounds__(256) void attn_kernel(
    const int* __restrict__ q_data,
    const float* __restrict__ q_table,
    const float* __restrict__ key_memory,
    float* __restrict__ w_out)
{
    __shared__ float ksm[32 * 129];
    int tid = threadIdx.x;
    for (int i = tid; i < 32 * 128; i += 256) {
        int m = i >> 7, k = i & 127;
        ksm[m * 129 + k] = key_memory[i];
    }
    __syncthreads();

    int warp = tid >> 5, lane = tid & 31;
    int t = blockIdx.x * 8 + warp;
    int row = q_data[t];

    float4 v = *(const float4*)(q_table + (size_t)row * 128 + lane * 4);
    uint2 hh, ll;
    hh.x = pack_hi(v.x, v.y); hh.y = pack_hi(v.z, v.w);
    ll.x = pack_lo(v.x, v.y); ll.y = pack_lo(v.z, v.w);
    *(uint2*)(g_qe_h + (size_t)t * 128 + lane * 4) = hh;
    *(uint2*)(g_qe_l + (size_t)t * 128 + lane * 4) = ll;

    float lg = 0.f;
    #pragma unroll
    for (int k = 0; k < 128; ++k) {
        float comp = ((k & 3) == 0) ? v.x : ((k & 3) == 1) ? v.y : ((k & 3) == 2) ? v.z : v.w;
        float qv = __shfl_sync(0xffffffffu, comp, k >> 2);
        lg = fmaf(qv, ksm[lane * 129 + k], lg);
    }
    float mx = lg;
    #pragma unroll
    for (int off = 16; off > 0; off >>= 1)
        mx = fmaxf(mx, __shfl_xor_sync(0xffffffffu, mx, off));
    float e = expf(lg - mx);
    float sum = e;
    #pragma unroll
    for (int off = 16; off > 0; off >>= 1)
        sum += __shfl_xor_sync(0xffffffffu, sum, off);
    w_out[(size_t)t * 32 + lane] = e / sum;
}

// ---------------- bf16x3 GEMM: streamed A+B 3-stage ring, 1 sync/chunk ----------------
struct GDesc {
    const __nv_bfloat16 *a0h, *a0l; int p0, o0;
    const __nv_bfloat16 *a1h, *a1l; int p1, o1;
    const __nv_bfloat16 *wh, *wl;   int ldk, wcol;
    const float* bias;
    int act;
    int omode;      // 0 fp32 store, 1 bf16 hi/lo store, 2 dot-reduce (no store)
    float* outf; int ldo, ocol;
    __nv_bfloat16 *oh, *ol; int ldob, ocolb;
    const float* w2;   // dot vector (omode 2), indexed at [ocol + col]
    float* pout;       // per-token dot output (omode 2)
};

__device__ __forceinline__ void mma16816(float* c, const uint32_t* a, const uint32_t* b) {
    asm volatile(
        "mma.sync.aligned.m16n8k16.row.col.f32.bf16.bf16.f32 "
        "{%0,%1,%2,%3}, {%4,%5,%6,%7}, {%8,%9}, {%0,%1,%2,%3};"
        : "+f"(c[0]), "+f"(c[1]), "+f"(c[2]), "+f"(c[3])
        : "r"(a[0]), "r"(a[1]), "r"(a[2]), "r"(a[3]), "r"(b[0]), "r"(b[1]));
}
#define LDSM4(r, addr) \
    asm volatile("ldmatrix.sync.aligned.m8n8.x4.shared.b16 {%0,%1,%2,%3}, [%4];" \
        : "=r"((r)[0]), "=r"((r)[1]), "=r"((r)[2]), "=r"((r)[3]) : "r"(addr))

__device__ __forceinline__ void cpa16(uint32_t dst, const void* src) {
    asm volatile("cp.async.cg.shared.global [%0], [%1], 16;" :: "r"(dst), "l"(src));
}

constexpr int APL = 8192;            // plane bytes (128 rows x 64 B)
constexpr int STG = 4 * APL;         // stage: A_hi A_lo B_hi B_lo = 32768
constexpr int GSM = 3 * STG;         // 98304 -> 2 CTAs/SM

__device__ __forceinline__ void prefetch_chunk(const GDesc& G, int tok0, int c,
                                               uint32_t st, int tid)
{
    int kbase = c << 5;
    const __nv_bfloat16 *Ah, *Al; int Ap, Ao;
    if (kbase < 128) { Ah = G.a0h; Al = G.a0l; Ap = G.p0; Ao = G.o0 + kbase; }
    else             { Ah = G.a1h; Al = G.a1l; Ap = G.p1; Ao = G.o1 + kbase - 128; }
    #pragma unroll
    for (int j = 0; j < 2; ++j) {
        int e = tid + j * 256;
        int r = e >> 2, q = e & 3;
        int qs = q ^ ((r >> 1) & 3);
        size_t asrc = (size_t)(tok0 + r) * Ap + Ao + q * 8;
        uint32_t adst = st + (uint32_t)(r * 64 + qs * 16);
        cpa16(adst,       Ah + asrc);
        cpa16(adst + APL, Al + asrc);
        size_t bsrc = (size_t)(G.wcol + r) * G.ldk + kbase + q * 8;
        uint32_t bdst = adst + 2u * APL;
        cpa16(bdst,       G.wh + bsrc);
        cpa16(bdst + APL, G.wl + bsrc);
    }
}

__global__ __launch_bounds__(256, 2) void mma_gemm(int Ktot, GDesc G0, GDesc G1, GDesc G2)
{
    extern __shared__ __align__(16) uint32_t smw[];
    uint32_t sbase = (uint32_t)__cvta_generic_to_shared(smw);

    const GDesc G = (blockIdx.y == 0) ? G0 : ((blockIdx.y == 1) ? G1 : G2);

    int tid  = threadIdx.x;
    int wid  = tid >> 5, lane = tid & 31;
    int g    = lane >> 2, tq = lane & 3;
    int tok0 = blockIdx.x * 128;

    int wm = (wid & 1) * 64;
    int wn = (wid >> 1) * 32;

    // hoisted fragment address components (row stride 64 B both A and B)
    int lane_r = lane & 15;
    int a_qb   = lane >> 4;                 // 0/1
    int jb     = lane >> 3;
    uint32_t a_row[4]; int a_sw[4];
    #pragma unroll
    for (int mt = 0; mt < 4; ++mt) {
        int r = wm + mt * 16 + lane_r;
        a_row[mt] = (uint32_t)(r * 64);
        a_sw[mt]  = (r >> 1) & 3;
    }
    uint32_t b_row[2]; int b_sw[2];
    #pragma unroll
    for (int ntp = 0; ntp < 2; ++ntp) {
        int n = wn + ntp * 16 + ((jb >> 1) * 8) + (lane & 7);
        b_row[ntp] = (uint32_t)(n * 64);
        b_sw[ntp]  = (n >> 1) & 3;
    }
    int b_qb = jb & 1;

    float acc[4][4][4];
    #pragma unroll
    for (int i = 0; i < 4; ++i)
        #pragma unroll
        for (int j = 0; j < 4; ++j)
            #pragma unroll
            for (int u = 0; u < 4; ++u) acc[i][j][u] = 0.f;

    int nch = Ktot >> 5;   // KC = 32

    prefetch_chunk(G, tok0, 0, sbase, tid);
    asm volatile("cp.async.commit_group;");
    prefetch_chunk(G, tok0, 1, sbase + STG, tid);
    asm volatile("cp.async.commit_group;");

    for (int c = 0; c < nch; ++c) {
        asm volatile("cp.async.wait_group 1;");
        __syncthreads();
        if (c + 2 < nch)
            prefetch_chunk(G, tok0, c + 2, sbase + (uint32_t)((c + 2) % 3) * STG, tid);
        asm volatile("cp.async.commit_group;");

        uint32_t Ab = sbase + (uint32_t)(c % 3) * STG;
        uint32_t Bb = Ab + 2u * APL;

        #pragma unroll
        for (int h = 0; h < 2; ++h) {
            uint32_t ah[4][4], al[4][4], bh[2][4], bl[2][4];
            int aq = h * 2 + a_qb;
            #pragma unroll
            for (int mt = 0; mt < 4; ++mt) {
                uint32_t addr = Ab + a_row[mt] + (uint32_t)((aq ^ a_sw[mt]) << 4);
                LDSM4(ah[mt], addr);
                LDSM4(al[mt], addr + APL);
            }
            int bq = h * 2 + b_qb;
            #pragma unroll
            for (int ntp = 0; ntp < 2; ++ntp) {
                uint32_t addr = Bb + b_row[ntp] + (uint32_t)((bq ^ b_sw[ntp]) << 4);
                LDSM4(bh[ntp], addr);
                LDSM4(bl[ntp], addr + APL);
            }
            #pragma unroll
            for (int mt = 0; mt < 4; ++mt)
                #pragma unroll
                for (int nt = 0; nt < 4; ++nt)
                    mma16816(acc[mt][nt], ah[mt], &bh[nt >> 1][(nt & 1) * 2]);
            #pragma unroll
            for (int mt = 0; mt < 4; ++mt)
                #pragma unroll
                for (int nt = 0; nt < 4; ++nt)
                    mma16816(acc[mt][nt], ah[mt], &bl[nt >> 1][(nt & 1) * 2]);
            #pragma unroll
            for (int mt = 0; mt < 4; ++mt)
                #pragma unroll
                for (int nt = 0; nt < 4; ++nt)
                    mma16816(acc[mt][nt], al[mt], &bh[nt >> 1][(nt & 1) * 2]);
        }
    }

    // ---------------- epilogue ----------------
    if (G.omode != 2) {
        #pragma unroll
        for (int nt = 0; nt < 4; ++nt) {
            int col = wn + nt * 8 + tq * 2;
            float2 bv = *(const float2*)(G.bias + col);
            #pragma unroll
            for (int mt = 0; mt < 4; ++mt) {
                int r0 = tok0 + wm + mt * 16 + g;
                float o00 = actf(acc[mt][nt][0] + bv.x, G.act);
                float o01 = actf(acc[mt][nt][1] + bv.y, G.act);
                float o10 = actf(acc[mt][nt][2] + bv.x, G.act);
                float o11 = actf(acc[mt][nt][3] + bv.y, G.act);
                if (G.omode == 0) {
                    *(float2*)(G.outf + (size_t)r0 * G.ldo + G.ocol + col)     = make_float2(o00, o01);
                    *(float2*)(G.outf + (size_t)(r0+8) * G.ldo + G.ocol + col) = make_float2(o10, o11);
                } else {
                    *(uint32_t*)(G.oh + (size_t)r0 * G.ldob + G.ocolb + col)     = pack_hi(o00, o01);
                    *(uint32_t*)(G.ol + (size_t)r0 * G.ldob + G.ocolb + col)     = pack_lo(o00, o01);
                    *(uint32_t*)(G.oh + (size_t)(r0+8) * G.ldob + G.ocolb + col) = pack_hi(o10, o11);
                    *(uint32_t*)(G.ol + (size_t)(r0+8) * G.ldob + G.ocolb + col) = pack_lo(o10, o11);
                }
            }
        }
    } else {
        // dot-reduce epilogue: out = act(acc+bias), partial = dot(out_row, w2), deterministic
        float p0[4] = {0,0,0,0}, p1[4] = {0,0,0,0};
        #pragma unroll
        for (int nt = 0; nt < 4; ++nt) {
            int col = wn + nt * 8 + tq * 2;
            float2 bv = *(const float2*)(G.bias + col);
            float2 wv = *(const float2*)(G.w2 + G.ocol + col);
            #pragma unroll
            for (int mt = 0; mt < 4; ++mt) {
                float o00 = actf(acc[mt][nt][0] + bv.x, G.act);
                float o01 = actf(acc[mt][nt][1] + bv.y, G.act);
                float o10 = actf(acc[mt][nt][2] + bv.x, G.act);
                float o11 = actf(acc[mt][nt][3] + bv.y, G.act);
                p0[mt] += o00 * wv.x + o01 * wv.y;
                p1[mt] += o10 * wv.x + o11 * wv.y;
            }
        }
        #pragma unroll
        for (int mt = 0; mt < 4; ++mt) {
            p0[mt] += __shfl_xor_sync(0xffffffffu, p0[mt], 1);
            p0[mt] += __shfl_xor_sync(0xffffffffu, p0[mt], 2);
            p1[mt] += __shfl_xor_sync(0xffffffffu, p1[mt], 1);
            p1[mt] += __shfl_xor_sync(0xffffffffu, p1[mt], 2);
        }
        float* red = (float*)smw;   // reuse pipeline smem
        __syncthreads();
        if (tq == 0) {
            #pragma unroll
            for (int mt = 0; mt < 4; ++mt) {
                int r = wm + mt * 16 + g;
                red[r * 4 + (wid >> 1)]       = p0[mt];
                red[(r + 8) * 4 + (wid >> 1)] = p1[mt];
            }
        }
        __syncthreads();
        if (tid < 128)
            G.pout[tok0 + tid] = red[tid*4] + red[tid*4+1] + red[tid*4+2] + red[tid*4+3];
    }
}

// ---------------- DKVMN scan ----------------
__global__ __launch_bounds__(256) void scan_kernel(const float* __restrict__ ivm)
{
    int b   = blockIdx.x;
    int dh  = blockIdx.y * 64;
    int tid = threadIdx.x;
    int dl  = tid >> 2, mq = tid & 3;
    int d   = dh + dl;
    size_t tb = (size_t)b * S;

    float Mv[8];
    #pragma unroll
    for (int m = 0; m < 8; ++m)
        Mv[m] = ivm[(mq * 8 + m) * 128 + d];

    __shared__ float wsm[2][4][32];

    float e[4], a[4];
    if (tid < 128)
        wsm[0][tid >> 5][tid & 31] = g_w[(tb + (tid >> 5)) * 32 + (tid & 31)];
    #pragma unroll
    for (int s = 0; s < 4; ++s) {
        e[s] = g_erase[(tb + s) * 128 + d];
        a[s] = g_add  [(tb + s) * 128 + d];
    }
    __syncthreads();

    for (int gg = 0; gg < S / 4; ++gg) {
        int cur = gg & 1, nxt = cur ^ 1;
        int sbase = gg * 4;
        float en[4], an[4];
        if (gg + 1 < S / 4) {
            if (tid < 128)
                wsm[nxt][tid >> 5][tid & 31] = g_w[(tb + sbase + 4 + (tid >> 5)) * 32 + (tid & 31)];
            #pragma unroll
            for (int s = 0; s < 4; ++s) {
                en[s] = g_erase[(tb + sbase + 4 + s) * 128 + d];
                an[s] = g_add  [(tb + sbase + 4 + s) * 128 + d];
            }
        } else {
            #pragma unroll
            for (int s = 0; s < 4; ++s) { en[s] = 0.f; an[s] = 0.f; }
        }

        #pragma unroll
        for (int s = 0; s < 4; ++s) {
            float r = 0.f;
            #pragma unroll
            for (int m = 0; m < 8; ++m) {
                float wm = wsm[cur][s][mq * 8 + m];
                r = fmaf(wm, Mv[m], r);                        // read BEFORE write
                Mv[m] = fmaf(wm, fmaf(-Mv[m], e[s], a[s]), Mv[m]);
            }
            r += __shfl_xor_sync(0xffffffffu, r, 1);
            r += __shfl_xor_sync(0xffffffffu, r, 2);
            if (mq == 0) {
                __nv_bfloat16 h = __float2bfloat16(r);
                g_rd_h[(tb + sbase + s) * 128 + d] = h;
                g_rd_l[(tb + sbase + s) * 128 + d] = __float2bfloat16(r - __bfloat162float(h));
            }
        }
        __syncthreads();
        #pragma unroll
        for (int s = 0; s < 4; ++s) { e[s] = en[s]; a[s] = an[s]; }
    }
}

// ---------------- combine heads ----------------
__global__ __launch_bounds__(256) void combine_kernel(
    const float* __restrict__ b_ab2, const float* __restrict__ b_df2,
    float* __restrict__ out)
{
    int t = blockIdx.x * 256 + threadIdx.x;
    float pa = g_pa[t] + g_pa[(size_t)T + t] + b_ab2[0];
    float pd = g_pd[t] + b_df2[0];
    float z    = 3.0f * pa - pd;
    float pred = 1.f / (1.f + expf(-z));
    out[t]               = pred;
    out[(size_t)T + t]   = pa;
    out[(size_t)2*T + t] = pd;
    out[(size_t)3*T + t] = z;
}

// ---------------- host launch ----------------
extern "C" void kernel_launch(void* const* d_in, const int* in_sizes, int n_in,
                              void* d_out, int out_size)
{
    const int*   q_data   = (const int*)  d_in[0];
    const int*   qa_data  = (const int*)  d_in[1];
    const float* q_table  = (const float*)d_in[2];
    const float* qa_table = (const float*)d_in[3];
    const float* key_mem  = (const float*)d_in[4];
    const float* init_vm  = (const float*)d_in[5];
    const float* W_erase  = (const float*)d_in[6];
    const float* b_erase  = (const float*)d_in[7];
    const float* W_add    = (const float*)d_in[8];
    const float* b_add    = (const float*)d_in[9];
    const float* W_sum    = (const float*)d_in[10];
    const float* b_sum    = (const float*)d_in[11];
    const float* W_ab1    = (const float*)d_in[12];
    const float* b_ab1    = (const float*)d_in[13];
    const float* W_ab2    = (const float*)d_in[14];
    const float* b_ab2    = (const float*)d_in[15];
    const float* W_df1    = (const float*)d_in[16];
    const float* b_df1    = (const float*)d_in[17];
    const float* W_df2    = (const float*)d_in[18];
    const float* b_df2    = (const float*)d_in[19];
    float* out = (float*)d_out;

    float *pw, *per, *pad, *ppa, *ppd;
    __nv_bfloat16 *qeh, *qel, *qah, *qal, *rdh, *rdl, *smh, *sml;
    __nv_bfloat16 *Weh, *Wel, *Wah, *Wal, *Wdh, *Wdl, *Wsh, *Wsl, *Wbh, *Wbl;
    cudaGetSymbolAddress((void**)&pw,  g_w);
    cudaGetSymbolAddress((void**)&per, g_erase);
    cudaGetSymbolAddress((void**)&pad, g_add);
    cudaGetSymbolAddress((void**)&ppa, g_pa);
    cudaGetSymbolAddress((void**)&ppd, g_pd);
    cudaGetSymbolAddress((void**)&qeh, g_qe_h); cudaGetSymbolAddress((void**)&qel, g_qe_l);
    cudaGetSymbolAddress((void**)&qah, g_qa_h); cudaGetSymbolAddress((void**)&qal, g_qa_l);
    cudaGetSymbolAddress((void**)&rdh, g_rd_h); cudaGetSymbolAddress((void**)&rdl, g_rd_l);
    cudaGetSymbolAddress((void**)&smh, g_sm_h); cudaGetSymbolAddress((void**)&sml, g_sm_l);
    cudaGetSymbolAddress((void**)&Weh, g_We_h); cudaGetSymbolAddress((void**)&Wel, g_We_l);
    cudaGetSymbolAddress((void**)&Wah, g_Wa_h); cudaGetSymbolAddress((void**)&Wal, g_Wa_l);
    cudaGetSymbolAddress((void**)&Wdh, g_Wd_h); cudaGetSymbolAddress((void**)&Wdl, g_Wd_l);
    cudaGetSymbolAddress((void**)&Wsh, g_Ws_h); cudaGetSymbolAddress((void**)&Wsl, g_Ws_l);
    cudaGetSymbolAddress((void**)&Wbh, g_Wb_h); cudaGetSymbolAddress((void**)&Wbl, g_Wb_l);

    cudaFuncSetAttribute(mma_gemm, cudaFuncAttributeMaxDynamicSharedMemorySize, GSM);

    const int MT = T / 128;

    prep_weight_all<<<704, 256>>>(W_erase, W_add, W_df1, W_sum, W_ab1);
    prep_gather_qa<<<T / 8, 256>>>(qa_data, qa_table);
    attn_kernel<<<T / 8, 256>>>(q_data, q_table, key_mem, pw);

    // erase / add / df1(+df2 dot) fused (K=128)
    GDesc Ge = { qah, qal, 128, 0,  nullptr, nullptr, 0, 0,
                 Weh, Wel, 128, 0,  b_erase, 1, 0, per, 128, 0,
                 nullptr, nullptr, 0, 0,  nullptr, nullptr };
    GDesc Ga = { qah, qal, 128, 0,  nullptr, nullptr, 0, 0,
                 Wah, Wal, 128, 0,  b_add,   2, 0, pad, 128, 0,
                 nullptr, nullptr, 0, 0,  nullptr, nullptr };
    GDesc Gd = { qeh, qel, 128, 0,  nullptr, nullptr, 0, 0,
                 Wdh, Wdl, 128, 0,  b_df1,   2, 2, nullptr, 0, 0,
                 nullptr, nullptr, 0, 0,  W_df2, ppd };
    mma_gemm<<<dim3(MT, 3), 256, GSM>>>(128, Ge, Ga, Gd);

    scan_kernel<<<dim3(B, 2), 256>>>(init_vm);

    // summary = tanh([reads | qe] @ W_sum + b), K=256, out bf16 hi/lo
    GDesc Gs0 = { rdh, rdl, 128, 0,  qeh, qel, 128, 0,
                  Wsh, Wsl, 256, 0,    b_sum,       2, 1, nullptr, 0, 0,
                  smh, sml, 256, 0,    nullptr, nullptr };
    GDesc Gs1 = { rdh, rdl, 128, 0,  qeh, qel, 128, 0,
                  Wsh, Wsl, 256, 128,  b_sum + 128, 2, 1, nullptr, 0, 0,
                  smh, sml, 256, 128,  nullptr, nullptr };
    mma_gemm<<<dim3(MT, 2), 256, GSM>>>(256, Gs0, Gs1, Gs1);

    // ability: h = tanh(summary @ W_ab1 + b); pa_partial = dot(h_half, W_ab2_half)
    GDesc Gb0 = { smh, sml, 256, 0,  smh, sml, 256, 128,
                  Wbh, Wbl, 256, 0,    b_ab1,       2, 2, nullptr, 0, 0,
                  nullptr, nullptr, 0, 0,  W_ab2, ppa };
    GDesc Gb1 = { smh, sml, 256, 0,  smh, sml, 256, 128,
                  Wbh, Wbl, 256, 128,  b_ab1 + 128, 2, 2, nullptr, 0, 128,
                  nullptr, nullptr, 0, 0,  W_ab2, ppa + T };
    mma_gemm<<<dim3(MT, 2), 256, GSM>>>(256, Gb0, Gb1, Gb1);

    combine_kernel<<<T / 256, 256>>>(b_ab2, b_df2, out);
}

// round 9
// speedup vs baseline: 2.1484x; 1.0082x over previous
#include <cuda_runtime.h>
#include <cuda_bf16.h>
#include <math.h>
#include <stdint.h>

constexpr int B   = 256;
constexpr int S   = 512;
constexpr int T   = B * S;       // 131072 tokens
constexpr int MEM = 32;
constexpr int DK  = 128;
constexpr int DV  = 128;
constexpr int DS  = 256;

// ---------------- scratch ----------------
__device__ float g_w    [(size_t)T * MEM];
__device__ float g_erase[(size_t)T * DV];
__device__ float g_add  [(size_t)T * DV];
__device__ float g_pa   [(size_t)2 * T];    // ability partial dots (2 N-halves)
__device__ float g_pd   [(size_t)T];        // difficulty dot

__device__ __nv_bfloat16 g_qe_h[(size_t)T * 128], g_qe_l[(size_t)T * 128];
__device__ __nv_bfloat16 g_qa_h[(size_t)T * 128], g_qa_l[(size_t)T * 128];
__device__ __nv_bfloat16 g_rd_h[(size_t)T * 128], g_rd_l[(size_t)T * 128];
__device__ __nv_bfloat16 g_sm_h[(size_t)T * 256], g_sm_l[(size_t)T * 256];

__device__ __nv_bfloat16 g_We_h[128*128], g_We_l[128*128];
__device__ __nv_bfloat16 g_Wa_h[128*128], g_Wa_l[128*128];
__device__ __nv_bfloat16 g_Wd_h[128*128], g_Wd_l[128*128];
__device__ __nv_bfloat16 g_Ws_h[256*256], g_Ws_l[256*256];
__device__ __nv_bfloat16 g_Wb_h[256*256], g_Wb_l[256*256];

__device__ __forceinline__ float actf(float x, int a) {
    if (a == 1) return 1.f / (1.f + expf(-x));
    if (a == 2) return tanhf(x);
    return x;
}
__device__ __forceinline__ uint32_t pack_hi(float x, float y) {
    __nv_bfloat16 hx = __float2bfloat16(x);
    __nv_bfloat16 hy = __float2bfloat16(y);
    return ((uint32_t)__bfloat16_as_ushort(hy) << 16) | __bfloat16_as_ushort(hx);
}
__device__ __forceinline__ uint32_t pack_lo(float x, float y) {
    __nv_bfloat16 hx = __float2bfloat16(x);
    __nv_bfloat16 hy = __float2bfloat16(y);
    __nv_bfloat16 lx = __float2bfloat16(x - __bfloat162float(hx));
    __nv_bfloat16 ly = __float2bfloat16(y - __bfloat162float(hy));
    return ((uint32_t)__bfloat16_as_ushort(ly) << 16) | __bfloat16_as_ushort(lx);
}

// ---------------- prep: all 5 weights, one launch ----------------
__global__ __launch_bounds__(256) void prep_weight_all(
    const float* __restrict__ W0, const float* __restrict__ W1,
    const float* __restrict__ W2, const float* __restrict__ W3,
    const float* __restrict__ W4)
{
    int bid = blockIdx.x;
    const float* W; __nv_bfloat16 *th, *tl; int K, N, base;
    if (bid < 64)       { W = W0; th = g_We_h; tl = g_We_l; K = 128; N = 128; base = 0; }
    else if (bid < 128) { W = W1; th = g_Wa_h; tl = g_Wa_l; K = 128; N = 128; base = 64; }
    else if (bid < 192) { W = W2; th = g_Wd_h; tl = g_Wd_l; K = 128; N = 128; base = 128; }
    else if (bid < 448) { W = W3; th = g_Ws_h; tl = g_Ws_l; K = 256; N = 256; base = 192; }
    else                { W = W4; th = g_Wb_h; tl = g_Wb_l; K = 256; N = 256; base = 448; }
    int e = (bid - base) * 256 + threadIdx.x;
    int k = e / N, n = e - k * N;
    float v = W[e];
    __nv_bfloat16 h = __float2bfloat16(v);
    th[(size_t)n * K + k] = h;
    tl[(size_t)n * K + k] = __float2bfloat16(v - __bfloat162float(h));
}

// ---------------- prep: qa gather + fp32 -> bf16 hi/lo ----------------
__global__ __launch_bounds__(256) void prep_gather_qa(
    const int* __restrict__ qa_data, const float* __restrict__ qa_table)
{
    int t    = blockIdx.x * 8 + (threadIdx.x >> 5);
    int lane = threadIdx.x & 31;
    int row = qa_data[t];
    float4 v = *(const float4*)(qa_table + (size_t)row * 128 + lane * 4);
    uint2 h, l;
    h.x = pack_hi(v.x, v.y); h.y = pack_hi(v.z, v.w);
    l.x = pack_lo(v.x, v.y); l.y = pack_lo(v.z, v.w);
    *(uint2*)(g_qa_h + (size_t)t * 128 + lane * 4) = h;
    *(uint2*)(g_qa_l + (size_t)t * 128 + lane * 4) = l;
}

// ---------------- attention softmax + qe bf16 conversion ----------------
__global__ __launch_bounds__(256) void attn_kernel(
    const int* __restrict__ q_data,
    const float* __restrict__ q_table,
    const float* __restrict__ key_memory,
    float* __restrict__ w_out)
{
    __shared__ float ksm[32 * 129];
    int tid = threadIdx.x;
    for (int i = tid; i < 32 * 128; i += 256) {
        int m = i >> 7, k = i & 127;
        ksm[m * 129 + k] = key_memory[i];
    }
    __syncthreads();

    int warp = tid >> 5, lane = tid & 31;
    int t = blockIdx.x * 8 + warp;
    int row = q_data[t];

    float4 v = *(const float4*)(q_table + (size_t)row * 128 + lane * 4);
    uint2 hh, ll;
    hh.x = pack_hi(v.x, v.y); hh.y = pack_hi(v.z, v.w);
    ll.x = pack_lo(v.x, v.y); ll.y = pack_lo(v.z, v.w);
    *(uint2*)(g_qe_h + (size_t)t * 128 + lane * 4) = hh;
    *(uint2*)(g_qe_l + (size_t)t * 128 + lane * 4) = ll;

    float lg = 0.f;
    #pragma unroll
    for (int k = 0; k < 128; ++k) {
        float comp = ((k & 3) == 0) ? v.x : ((k & 3) == 1) ? v.y : ((k & 3) == 2) ? v.z : v.w;
        float qv = __shfl_sync(0xffffffffu, comp, k >> 2);
        lg = fmaf(qv, ksm[lane * 129 + k], lg);
    }
    float mx = lg;
    #pragma unroll
    for (int off = 16; off > 0; off >>= 1)
        mx = fmaxf(mx, __shfl_xor_sync(0xffffffffu, mx, off));
    float e = expf(lg - mx);
    float sum = e;
    #pragma unroll
    for (int off = 16; off > 0; off >>= 1)
        sum += __shfl_xor_sync(0xffffffffu, sum, off);
    w_out[(size_t)t * 32 + lane] = e / sum;
}

// ---------------- bf16x3 GEMM: B-resident, 3-stage A ring, 1 sync/chunk ----------------
struct GDesc {
    const __nv_bfloat16 *a0h, *a0l; int p0, o0;
    const __nv_bfloat16 *a1h, *a1l; int p1, o1;
    const __nv_bfloat16 *wh, *wl;   int ldk, wcol;
    const float* bias;
    int act;
    int omode;      // 0 fp32 store, 1 bf16 hi/lo store, 2 dot-reduce (no store)
    float* outf; int ldo, ocol;
    __nv_bfloat16 *oh, *ol; int ldob, ocolb;
    const float* w2;   // dot vector (omode 2), indexed at [ocol + col]
    float* pout;       // per-token dot output (omode 2)
};

__device__ __forceinline__ void mma16816(float* c, const uint32_t* a, const uint32_t* b) {
    asm volatile(
        "mma.sync.aligned.m16n8k16.row.col.f32.bf16.bf16.f32 "
        "{%0,%1,%2,%3}, {%4,%5,%6,%7}, {%8,%9}, {%0,%1,%2,%3};"
        : "+f"(c[0]), "+f"(c[1]), "+f"(c[2]), "+f"(c[3])
        : "r"(a[0]), "r"(a[1]), "r"(a[2]), "r"(a[3]), "r"(b[0]), "r"(b[1]));
}
#define LDSM4(r, addr) \
    asm volatile("ldmatrix.sync.aligned.m8n8.x4.shared.b16 {%0,%1,%2,%3}, [%4];" \
        : "=r"((r)[0]), "=r"((r)[1]), "=r"((r)[2]), "=r"((r)[3]) : "r"(addr))

__device__ __forceinline__ void cpa16(uint32_t dst, const void* src) {
    asm volatile("cp.async.cg.shared.global [%0], [%1], 16;" :: "r"(dst), "l"(src));
}

constexpr int APL  = 8192;           // A plane bytes per stage (128 rows x 64 B)
constexpr int AST  = 2 * APL;        // A stage (hi+lo) = 16384
constexpr int BPL  = 32768;          // B plane bytes (128 rows x 256 B)
constexpr int AOFF = 2 * BPL;        // 65536
constexpr int GSM  = AOFF + 3 * AST; // 114688 -> 2 CTAs/SM

// A chunk: 128 rows x 32 halves. granule swizzle q' = q ^ ((r>>1)&3)
__device__ __forceinline__ void prefetch_A(const GDesc& G, int tok0, int c,
                                           uint32_t stage_base, int tid)
{
    int kbase = c << 5;
    const __nv_bfloat16 *Ah, *Al; int Ap, Ao;
    if (kbase < 128) { Ah = G.a0h; Al = G.a0l; Ap = G.p0; Ao = G.o0 + kbase; }
    else             { Ah = G.a1h; Al = G.a1l; Ap = G.p1; Ao = G.o1 + kbase - 128; }
    #pragma unroll
    for (int j = 0; j < 2; ++j) {
        int e = tid + j * 256;
        int r = e >> 2, q = e & 3;
        int qs = q ^ ((r >> 1) & 3);
        size_t src = (size_t)(tok0 + r) * Ap + Ao + q * 8;
        uint32_t dst = stage_base + (uint32_t)(r * 64 + qs * 16);
        cpa16(dst,       Ah + src);
        cpa16(dst + APL, Al + src);
    }
}

// B half: 128 n-rows x 128 k-halves. granule swizzle q' = q ^ (n&7)
__device__ __forceinline__ void load_B(const GDesc& G, int khalf, uint32_t sbase, int tid)
{
    #pragma unroll
    for (int j = 0; j < 8; ++j) {
        int e = tid + j * 256;
        int n = e >> 4, q = e & 15;
        int qs = q ^ (n & 7);
        size_t src = (size_t)(G.wcol + n) * G.ldk + khalf + q * 8;
        uint32_t dst = sbase + (uint32_t)(n * 256 + qs * 16);
        cpa16(dst,       G.wh + src);
        cpa16(dst + BPL, G.wl + src);
    }
}

__global__ __launch_bounds__(256, 2) void mma_gemm(int Ktot, GDesc G0, GDesc G1, GDesc G2)
{
    extern __shared__ __align__(16) uint32_t smw[];
    uint32_t sbase = (uint32_t)__cvta_generic_to_shared(smw);

    const GDesc G = (blockIdx.y == 0) ? G0 : ((blockIdx.y == 1) ? G1 : G2);

    int tid  = threadIdx.x;
    int wid  = tid >> 5, lane = tid & 31;
    int g    = lane >> 2, tq = lane & 3;
    int tok0 = blockIdx.x * 128;

    int wm = (wid & 1) * 64;
    int wn = (wid >> 1) * 32;

    // hoisted fragment address components
    int lane_r = lane & 15;
    int a_qb   = lane >> 4;                 // 0/1
    int jb     = lane >> 3;
    uint32_t a_row[4]; int a_sw[4];
    #pragma unroll
    for (int mt = 0; mt < 4; ++mt) {
        int r = wm + mt * 16 + lane_r;
        a_row[mt] = (uint32_t)(r * 64);
        a_sw[mt]  = (r >> 1) & 3;
    }
    uint32_t b_row[2]; int b_sw[2];
    #pragma unroll
    for (int ntp = 0; ntp < 2; ++ntp) {
        int n = wn + ntp * 16 + ((jb >> 1) * 8) + (lane & 7);
        b_row[ntp] = (uint32_t)(n * 256);
        b_sw[ntp]  = n & 7;
    }
    int b_qb = jb & 1;

    float acc[4][4][4];
    #pragma unroll
    for (int i = 0; i < 4; ++i)
        #pragma unroll
        for (int j = 0; j < 4; ++j)
            #pragma unroll
            for (int u = 0; u < 4; ++u) acc[i][j][u] = 0.f;

    int nch = Ktot >> 5;   // KC = 32

    // prologue: B half0 + A0 (group0), A1 (group1)
    load_B(G, 0, sbase, tid);
    prefetch_A(G, tok0, 0, sbase + AOFF, tid);
    asm volatile("cp.async.commit_group;");
    if (nch > 1) prefetch_A(G, tok0, 1, sbase + AOFF + AST, tid);
    asm volatile("cp.async.commit_group;");

    for (int c = 0; c < nch; ++c) {
        asm volatile("cp.async.wait_group 1;");
        __syncthreads();
        if (c == 4) {                         // only reached when nch == 8: B swap
            load_B(G, 128, sbase, tid);
            if (c + 2 < nch) {
                int s = (c + 2) % 3;
                prefetch_A(G, tok0, c + 2, sbase + AOFF + (uint32_t)s * AST, tid);
            }
            asm volatile("cp.async.commit_group;");
            asm volatile("cp.async.wait_group 0;");
            __syncthreads();
        } else {
            if (c + 2 < nch) {
                int s = (c + 2) % 3;
                prefetch_A(G, tok0, c + 2, sbase + AOFF + (uint32_t)s * AST, tid);
            }
            asm volatile("cp.async.commit_group;");
        }

        uint32_t Ab = sbase + AOFF + (uint32_t)(c % 3) * AST;
        int bq_c = (c & 3) * 4 + b_qb;

        #pragma unroll
        for (int h = 0; h < 2; ++h) {
            uint32_t ah[4][4], al[4][4], bh[2][4], bl[2][4];
            int aq = h * 2 + a_qb;
            #pragma unroll
            for (int mt = 0; mt < 4; ++mt) {
                uint32_t addr = Ab + a_row[mt] + (uint32_t)((aq ^ a_sw[mt]) << 4);
                LDSM4(ah[mt], addr);
                LDSM4(al[mt], addr + APL);
            }
            int bq = bq_c + h * 2;
            #pragma unroll
            for (int ntp = 0; ntp < 2; ++ntp) {
                uint32_t addr = sbase + b_row[ntp] + (uint32_t)((bq ^ b_sw[ntp]) << 4);
                LDSM4(bh[ntp], addr);
                LDSM4(bl[ntp], addr + BPL);
            }
            #pragma unroll
            for (int mt = 0; mt < 4; ++mt)
                #pragma unroll
                for (int nt = 0; nt < 4; ++nt)
                    mma16816(acc[mt][nt], ah[mt], &bh[nt >> 1][(nt & 1) * 2]);
            #pragma unroll
            for (int mt = 0; mt < 4; ++mt)
                #pragma unroll
                for (int nt = 0; nt < 4; ++nt)
                    mma16816(acc[mt][nt], ah[mt], &bl[nt >> 1][(nt & 1) * 2]);
            #pragma unroll
            for (int mt = 0; mt < 4; ++mt)
                #pragma unroll
                for (int nt = 0; nt < 4; ++nt)
                    mma16816(acc[mt][nt], al[mt], &bh[nt >> 1][(nt & 1) * 2]);
        }
    }

    // ---------------- epilogue ----------------
    if (G.omode != 2) {
        #pragma unroll
        for (int nt = 0; nt < 4; ++nt) {
            int col = wn + nt * 8 + tq * 2;
            float2 bv = *(const float2*)(G.bias + col);
            #pragma unroll
            for (int mt = 0; mt < 4; ++mt) {
                int r0 = tok0 + wm + mt * 16 + g;
                float o00 = actf(acc[mt][nt][0] + bv.x, G.act);
                float o01 = actf(acc[mt][nt][1] + bv.y, G.act);
                float o10 = actf(acc[mt][nt][2] + bv.x, G.act);
                float o11 = actf(acc[mt][nt][3] + bv.y, G.act);
                if (G.omode == 0) {
                    *(float2*)(G.outf + (size_t)r0 * G.ldo + G.ocol + col)     = make_float2(o00, o01);
                    *(float2*)(G.outf + (size_t)(r0+8) * G.ldo + G.ocol + col) = make_float2(o10, o11);
                } else {
                    *(uint32_t*)(G.oh + (size_t)r0 * G.ldob + G.ocolb + col)     = pack_hi(o00, o01);
                    *(uint32_t*)(G.ol + (size_t)r0 * G.ldob + G.ocolb + col)     = pack_lo(o00, o01);
                    *(uint32_t*)(G.oh + (size_t)(r0+8) * G.ldob + G.ocolb + col) = pack_hi(o10, o11);
                    *(uint32_t*)(G.ol + (size_t)(r0+8) * G.ldob + G.ocolb + col) = pack_lo(o10, o11);
                }
            }
        }
    } else {
        // dot-reduce epilogue: out = act(acc+bias), partial = dot(out_row, w2), deterministic
        float p0[4] = {0,0,0,0}, p1[4] = {0,0,0,0};
        #pragma unroll
        for (int nt = 0; nt < 4; ++nt) {
            int col = wn + nt * 8 + tq * 2;
            float2 bv = *(const float2*)(G.bias + col);
            float2 wv = *(const float2*)(G.w2 + G.ocol + col);
            #pragma unroll
            for (int mt = 0; mt < 4; ++mt) {
                float o00 = actf(acc[mt][nt][0] + bv.x, G.act);
                float o01 = actf(acc[mt][nt][1] + bv.y, G.act);
                float o10 = actf(acc[mt][nt][2] + bv.x, G.act);
                float o11 = actf(acc[mt][nt][3] + bv.y, G.act);
                p0[mt] += o00 * wv.x + o01 * wv.y;
                p1[mt] += o10 * wv.x + o11 * wv.y;
            }
        }
        #pragma unroll
        for (int mt = 0; mt < 4; ++mt) {
            p0[mt] += __shfl_xor_sync(0xffffffffu, p0[mt], 1);
            p0[mt] += __shfl_xor_sync(0xffffffffu, p0[mt], 2);
            p1[mt] += __shfl_xor_sync(0xffffffffu, p1[mt], 1);
            p1[mt] += __shfl_xor_sync(0xffffffffu, p1[mt], 2);
        }
        float* red = (float*)smw;   // reuse pipeline smem
        __syncthreads();
        if (tq == 0) {
            #pragma unroll
            for (int mt = 0; mt < 4; ++mt) {
                int r = wm + mt * 16 + g;
                red[r * 4 + (wid >> 1)]       = p0[mt];
                red[(r + 8) * 4 + (wid >> 1)] = p1[mt];
            }
        }
        __syncthreads();
        if (tid < 128)
            G.pout[tok0 + tid] = red[tid*4] + red[tid*4+1] + red[tid*4+2] + red[tid*4+3];
    }
}

// ---------------- DKVMN scan ----------------
__global__ __launch_bounds__(256) void scan_kernel(const float* __restrict__ ivm)
{
    int b   = blockIdx.x;
    int dh  = blockIdx.y * 64;
    int tid = threadIdx.x;
    int dl  = tid >> 2, mq = tid & 3;
    int d   = dh + dl;
    size_t tb = (size_t)b * S;

    float Mv[8];
    #pragma unroll
    for (int m = 0; m < 8; ++m)
        Mv[m] = ivm[(mq * 8 + m) * 128 + d];

    __shared__ float wsm[2][4][32];

    float e[4], a[4];
    if (tid < 128)
        wsm[0][tid >> 5][tid & 31] = g_w[(tb + (tid >> 5)) * 32 + (tid & 31)];
    #pragma unroll
    for (int s = 0; s < 4; ++s) {
        e[s] = g_erase[(tb + s) * 128 + d];
        a[s] = g_add  [(tb + s) * 128 + d];
    }
    __syncthreads();

    for (int gg = 0; gg < S / 4; ++gg) {
        int cur = gg & 1, nxt = cur ^ 1;
        int sbase = gg * 4;
        float en[4], an[4];
        if (gg + 1 < S / 4) {
            if (tid < 128)
                wsm[nxt][tid >> 5][tid & 31] = g_w[(tb + sbase + 4 + (tid >> 5)) * 32 + (tid & 31)];
            #pragma unroll
            for (int s = 0; s < 4; ++s) {
                en[s] = g_erase[(tb + sbase + 4 + s) * 128 + d];
                an[s] = g_add  [(tb + sbase + 4 + s) * 128 + d];
            }
        } else {
            #pragma unroll
            for (int s = 0; s < 4; ++s) { en[s] = 0.f; an[s] = 0.f; }
        }

        #pragma unroll
        for (int s = 0; s < 4; ++s) {
            float r = 0.f;
            #pragma unroll
            for (int m = 0; m < 8; ++m) {
                float wm = wsm[cur][s][mq * 8 + m];
                r = fmaf(wm, Mv[m], r);                        // read BEFORE write
                Mv[m] = fmaf(wm, fmaf(-Mv[m], e[s], a[s]), Mv[m]);
            }
            r += __shfl_xor_sync(0xffffffffu, r, 1);
            r += __shfl_xor_sync(0xffffffffu, r, 2);
            if (mq == 0) {
                __nv_bfloat16 h = __float2bfloat16(r);
                g_rd_h[(tb + sbase + s) * 128 + d] = h;
                g_rd_l[(tb + sbase + s) * 128 + d] = __float2bfloat16(r - __bfloat162float(h));
            }
        }
        __syncthreads();
        #pragma unroll
        for (int s = 0; s < 4; ++s) { e[s] = en[s]; a[s] = an[s]; }
    }
}

// ---------------- combine heads ----------------
__global__ __launch_bounds__(256) void combine_kernel(
    const float* __restrict__ b_ab2, const float* __restrict__ b_df2,
    float* __restrict__ out)
{
    int t = blockIdx.x * 256 + threadIdx.x;
    float pa = g_pa[t] + g_pa[(size_t)T + t] + b_ab2[0];
    float pd = g_pd[t] + b_df2[0];
    float z    = 3.0f * pa - pd;
    float pred = 1.f / (1.f + expf(-z));
    out[t]               = pred;
    out[(size_t)T + t]   = pa;
    out[(size_t)2*T + t] = pd;
    out[(size_t)3*T + t] = z;
}

// ---------------- host launch ----------------
extern "C" void kernel_launch(void* const* d_in, const int* in_sizes, int n_in,
                              void* d_out, int out_size)
{
    const int*   q_data   = (const int*)  d_in[0];
    const int*   qa_data  = (const int*)  d_in[1];
    const float* q_table  = (const float*)d_in[2];
    const float* qa_table = (const float*)d_in[3];
    const float* key_mem  = (const float*)d_in[4];
    const float* init_vm  = (const float*)d_in[5];
    const float* W_erase  = (const float*)d_in[6];
    const float* b_erase  = (const float*)d_in[7];
    const float* W_add    = (const float*)d_in[8];
    const float* b_add    = (const float*)d_in[9];
    const float* W_sum    = (const float*)d_in[10];
    const float* b_sum    = (const float*)d_in[11];
    const float* W_ab1    = (const float*)d_in[12];
    const float* b_ab1    = (const float*)d_in[13];
    const float* W_ab2    = (const float*)d_in[14];
    const float* b_ab2    = (const float*)d_in[15];
    const float* W_df1    = (const float*)d_in[16];
    const float* b_df1    = (const float*)d_in[17];
    const float* W_df2    = (const float*)d_in[18];
    const float* b_df2    = (const float*)d_in[19];
    float* out = (float*)d_out;

    float *pw, *per, *pad, *ppa, *ppd;
    __nv_bfloat16 *qeh, *qel, *qah, *qal, *rdh, *rdl, *smh, *sml;
    __nv_bfloat16 *Weh, *Wel, *Wah, *Wal, *Wdh, *Wdl, *Wsh, *Wsl, *Wbh, *Wbl;
    cudaGetSymbolAddress((void**)&pw,  g_w);
    cudaGetSymbolAddress((void**)&per, g_erase);
    cudaGetSymbolAddress((void**)&pad, g_add);
    cudaGetSymbolAddress((void**)&ppa, g_pa);
    cudaGetSymbolAddress((void**)&ppd, g_pd);
    cudaGetSymbolAddress((void**)&qeh, g_qe_h); cudaGetSymbolAddress((void**)&qel, g_qe_l);
    cudaGetSymbolAddress((void**)&qah, g_qa_h); cudaGetSymbolAddress((void**)&qal, g_qa_l);
    cudaGetSymbolAddress((void**)&rdh, g_rd_h); cudaGetSymbolAddress((void**)&rdl, g_rd_l);
    cudaGetSymbolAddress((void**)&smh, g_sm_h); cudaGetSymbolAddress((void**)&sml, g_sm_l);
    cudaGetSymbolAddress((void**)&Weh, g_We_h); cudaGetSymbolAddress((void**)&Wel, g_We_l);
    cudaGetSymbolAddress((void**)&Wah, g_Wa_h); cudaGetSymbolAddress((void**)&Wal, g_Wa_l);
    cudaGetSymbolAddress((void**)&Wdh, g_Wd_h); cudaGetSymbolAddress((void**)&Wdl, g_Wd_l);
    cudaGetSymbolAddress((void**)&Wsh, g_Ws_h); cudaGetSymbolAddress((void**)&Wsl, g_Ws_l);
    cudaGetSymbolAddress((void**)&Wbh, g_Wb_h); cudaGetSymbolAddress((void**)&Wbl, g_Wb_l);

    cudaFuncSetAttribute(mma_gemm, cudaFuncAttributeMaxDynamicSharedMemorySize, GSM);

    const int MT = T / 128;

    prep_weight_all<<<704, 256>>>(W_erase, W_add, W_df1, W_sum, W_ab1);
    prep_gather_qa<<<T / 8, 256>>>(qa_data, qa_table);
    attn_kernel<<<T / 8, 256>>>(q_data, q_table, key_mem, pw);

    // erase / add / df1(+df2 dot) fused (K=128)
    GDesc Ge = { qah, qal, 128, 0,  nullptr, nullptr, 0, 0,
                 Weh, Wel, 128, 0,  b_erase, 1, 0, per, 128, 0,
                 nullptr, nullptr, 0, 0,  nullptr, nullptr };
    GDesc Ga = { qah, qal, 128, 0,  nullptr, nullptr, 0, 0,
                 Wah, Wal, 128, 0,  b_add,   2, 0, pad, 128, 0,
                 nullptr, nullptr, 0, 0,  nullptr, nullptr };
    GDesc Gd = { qeh, qel, 128, 0,  nullptr, nullptr, 0, 0,
                 Wdh, Wdl, 128, 0,  b_df1,   2, 2, nullptr, 0, 0,
                 nullptr, nullptr, 0, 0,  W_df2, ppd };
    mma_gemm<<<dim3(MT, 3), 256, GSM>>>(128, Ge, Ga, Gd);

    scan_kernel<<<dim3(B, 2), 256>>>(init_vm);

    // summary = tanh([reads | qe] @ W_sum + b), K=256, out bf16 hi/lo
    GDesc Gs0 = { rdh, rdl, 128, 0,  qeh, qel, 128, 0,
                  Wsh, Wsl, 256, 0,    b_sum,       2, 1, nullptr, 0, 0,
                  smh, sml, 256, 0,    nullptr, nullptr };
    GDesc Gs1 = { rdh, rdl, 128, 0,  qeh, qel, 128, 0,
                  Wsh, Wsl, 256, 128,  b_sum + 128, 2, 1, nullptr, 0, 0,
                  smh, sml, 256, 128,  nullptr, nullptr };
    mma_gemm<<<dim3(MT, 2), 256, GSM>>>(256, Gs0, Gs1, Gs1);

    // ability: h = tanh(summary @ W_ab1 + b); pa_partial = dot(h_half, W_ab2_half)
    GDesc Gb0 = { smh, sml, 256, 0,  smh, sml, 256, 128,
                  Wbh, Wbl, 256, 0,    b_ab1,       2, 2, nullptr, 0, 0,
                  nullptr, nullptr, 0, 0,  W_ab2, ppa };
    GDesc Gb1 = { smh, sml, 256, 0,  smh, sml, 256, 128,
                  Wbh, Wbl, 256, 128,  b_ab1 + 128, 2, 2, nullptr, 0, 128,
                  nullptr, nullptr, 0, 0,  W_ab2, ppa + T };
    mma_gemm<<<dim3(MT, 2), 256, GSM>>>(256, Gb0, Gb1, Gb1);

    combine_kernel<<<T / 256, 256>>>(b_ab2, b_df2, out);
}